// round 8
// baseline (speedup 1.0000x reference)
#include <cuda_runtime.h>

#define NN 50000
#define NE 800000
#define HH 128
#define NG 128

// ---- scratch (device globals; no allocation allowed) ----
__device__ __align__(16) float g_agg[(size_t)NN * HH];   // 25.6 MB
__device__ __align__(16) float g_h1 [(size_t)NN * HH];
__device__ __align__(16) float g_h2 [(size_t)NN * HH];
__device__ float g_deg[NN];
__device__ float g_invdeg[NN];
__device__ __align__(16) float g_pool[NG * HH];
__device__ float g_gcnt[NG];

__device__ __forceinline__ void red_add_v4(float* p, float4 v) {
    asm volatile("red.global.add.v4.f32 [%0], {%1,%2,%3,%4};"
                 :: "l"(p), "f"(v.x), "f"(v.y), "f"(v.z), "f"(v.w)
                 : "memory");
}

// mode 0: zero agg + deg ; mode 1: zero agg ; mode 2: zero pool + gcnt
__global__ void zero_kernel(int mode) {
    long long i = (long long)blockIdx.x * blockDim.x + threadIdx.x;
    if (mode == 0) {
        if (i < (long long)NN * HH / 4) ((float4*)g_agg)[i] = make_float4(0,0,0,0);
        if (i < NN) g_deg[i] = 0.f;
    } else if (mode == 1) {
        if (i < (long long)NN * HH / 4) ((float4*)g_agg)[i] = make_float4(0,0,0,0);
    } else {
        if (i < NG * HH) g_pool[i] = 0.f;
        if (i < NG)      g_gcnt[i] = 0.f;
    }
}

// NOTE: edge_index / batch are int32 on device (JAX default x64-disabled
// silently downcasts jnp.int64 -> int32).
__global__ void deg_kernel(const int* __restrict__ ei) {
    int e = blockIdx.x * blockDim.x + threadIdx.x;
    if (e < NE) atomicAdd(&g_deg[ei[NE + e]], 1.0f);
}

__global__ void invdeg_kernel() {
    int i = blockIdx.x * blockDim.x + threadIdx.x;
    if (i < NN) g_invdeg[i] = 1.0f / fmaxf(g_deg[i], 1.0f);
}

// one warp per edge: gather feat[src] (float4/lane), vector-reduce into g_agg[dst]
// mode 0: feat = external x ; mode 1: feat = g_h1
__global__ void scatter_kernel(const float* __restrict__ xext,
                               const int* __restrict__ ei, int mode) {
    int w = (blockIdx.x * blockDim.x + threadIdx.x) >> 5;
    if (w >= NE) return;
    int lane = threadIdx.x & 31;
    const float* feat = (mode == 0) ? xext : g_h1;
    int src = ei[w];
    int dst = ei[NE + w];
    float4 v = ((const float4*)(feat + (size_t)src * HH))[lane];
    red_add_v4(g_agg + (size_t)dst * HH + (lane << 2), v);
}

// out = relu( (agg*invdeg) @ wl^T + b + xin @ wr^T )
// Concat-GEMM: M=NN, N=128, K=256. BM=BN=128, BK=32, 256 threads, 8x8 microtile.
// mode 0: xin = external x, out = g_h1 ; mode 1: xin = g_h1, out = g_h2
__global__ __launch_bounds__(256)
void gemm_fused(const float* __restrict__ xext,
                const float* __restrict__ wl, const float* __restrict__ wr,
                const float* __restrict__ bias, int mode) {
    __shared__ float As[32][128];
    __shared__ float Bs[32][128];

    const float* xin = (mode == 0) ? xext : g_h1;
    float*       out = (mode == 0) ? g_h1 : g_h2;

    int m0  = blockIdx.x * 128;
    int tid = threadIdx.x;
    int tr  = tid >> 4;     // 0..15 (row group)
    int tc  = tid & 15;     // 0..15 (col group)

    float acc[8][8];
    #pragma unroll
    for (int i = 0; i < 8; ++i)
        #pragma unroll
        for (int j = 0; j < 8; ++j) acc[i][j] = 0.f;

    #pragma unroll 1
    for (int half = 0; half < 2; ++half) {
        const float* A = half ? xin : g_agg;
        const float* W = half ? wr  : wl;
        #pragma unroll 1
        for (int kc = 0; kc < 128; kc += 32) {
            // load A tile (transposed into As[k][m]) and B tile (Bs[k][j] = W[j][k])
            #pragma unroll
            for (int i = 0; i < 4; ++i) {
                int idx = tid + i * 256;       // 0..1023 float4 slots
                int m   = idx >> 3;            // 0..127
                int c4  = idx & 7;             // k-offset group (4 floats each)
                int gm  = m0 + m;
                float4 v = make_float4(0.f, 0.f, 0.f, 0.f);
                if (gm < NN) {
                    v = *(const float4*)(A + (size_t)gm * HH + kc + (c4 << 2));
                    if (!half) {
                        float s = g_invdeg[gm];
                        v.x *= s; v.y *= s; v.z *= s; v.w *= s;
                    }
                }
                As[c4*4+0][m] = v.x; As[c4*4+1][m] = v.y;
                As[c4*4+2][m] = v.z; As[c4*4+3][m] = v.w;

                float4 wv = *(const float4*)(W + (size_t)m * HH + kc + (c4 << 2));
                Bs[c4*4+0][m] = wv.x; Bs[c4*4+1][m] = wv.y;
                Bs[c4*4+2][m] = wv.z; Bs[c4*4+3][m] = wv.w;
            }
            __syncthreads();
            #pragma unroll
            for (int k = 0; k < 32; ++k) {
                float4 a0 = *(const float4*)&As[k][tr * 8];
                float4 a1 = *(const float4*)&As[k][tr * 8 + 4];
                float4 b0 = *(const float4*)&Bs[k][tc * 8];
                float4 b1 = *(const float4*)&Bs[k][tc * 8 + 4];
                float a[8] = {a0.x,a0.y,a0.z,a0.w,a1.x,a1.y,a1.z,a1.w};
                float b[8] = {b0.x,b0.y,b0.z,b0.w,b1.x,b1.y,b1.z,b1.w};
                #pragma unroll
                for (int i = 0; i < 8; ++i)
                    #pragma unroll
                    for (int j = 0; j < 8; ++j)
                        acc[i][j] += a[i] * b[j];
            }
            __syncthreads();
        }
    }

    // epilogue: bias + relu
    #pragma unroll
    for (int i = 0; i < 8; ++i) {
        int gm = m0 + tr * 8 + i;
        if (gm >= NN) continue;
        #pragma unroll
        for (int j = 0; j < 8; j += 4) {
            float4 v;
            v.x = fmaxf(acc[i][j+0] + bias[tc*8 + j+0], 0.f);
            v.y = fmaxf(acc[i][j+1] + bias[tc*8 + j+1], 0.f);
            v.z = fmaxf(acc[i][j+2] + bias[tc*8 + j+2], 0.f);
            v.w = fmaxf(acc[i][j+3] + bias[tc*8 + j+3], 0.f);
            *(float4*)(out + (size_t)gm * HH + tc * 8 + j) = v;
        }
    }
}

// one warp per node: vector-reduce h2 row into g_pool[batch[node]]
__global__ void pool_kernel(const int* __restrict__ batch) {
    int w = (blockIdx.x * blockDim.x + threadIdx.x) >> 5;
    if (w >= NN) return;
    int lane = threadIdx.x & 31;
    int g = batch[w];
    float4 v = ((const float4*)(g_h2 + (size_t)w * HH))[lane];
    red_add_v4(g_pool + g * HH + (lane << 2), v);
    if (lane == 0) atomicAdd(&g_gcnt[g], 1.0f);
}

// out[g][j] = cb[j] + sum_k (pool[g][k]/cnt[g]) * cw[j][k]
__global__ void cls_kernel(const float* __restrict__ cw,
                           const float* __restrict__ cb,
                           float* __restrict__ out) {
    __shared__ float sh[HH];
    int g = blockIdx.x, j = threadIdx.x;
    float inv = 1.0f / fmaxf(g_gcnt[g], 1.0f);
    sh[j] = g_pool[g * HH + j] * inv;
    __syncthreads();
    float acc = 0.f;
    #pragma unroll 8
    for (int k = 0; k < HH; ++k)
        acc += sh[k] * cw[(size_t)j * HH + k];
    out[g * HH + j] = acc + cb[j];
}

extern "C" void kernel_launch(void* const* d_in, const int* in_sizes, int n_in,
                              void* d_out, int out_size) {
    const float* x    = (const float*)d_in[0];
    const int*   ei   = (const int*)d_in[1];    // int32 (JAX x64 disabled)
    const int*   batch= (const int*)d_in[2];    // int32
    const float* wl1 = (const float*)d_in[3];
    const float* b1  = (const float*)d_in[4];
    const float* wr1 = (const float*)d_in[5];
    const float* wl2 = (const float*)d_in[6];
    const float* b2  = (const float*)d_in[7];
    const float* wr2 = (const float*)d_in[8];
    const float* cw  = (const float*)d_in[9];
    const float* cb  = (const float*)d_in[10];
    float* out = (float*)d_out;

    const int zgrid   = (NN * HH / 4 + 255) / 256;       // 6250
    const int eggrid  = (NE + 255) / 256;                // 3125
    const int ngrid   = (NN + 255) / 256;                // 196
    const int scgrid  = (NE + 7) / 8;                    // 100000 (8 warps/block)
    const int gmgrid  = (NN + 127) / 128;                // 391
    const int plgrid  = (NN + 7) / 8;                    // 6250

    // layer 1
    zero_kernel<<<zgrid, 256>>>(0);
    deg_kernel<<<eggrid, 256>>>(ei);
    invdeg_kernel<<<ngrid, 256>>>();
    scatter_kernel<<<scgrid, 256>>>(x, ei, 0);
    gemm_fused<<<gmgrid, 256>>>(x, wl1, wr1, b1, 0);

    // layer 2
    zero_kernel<<<zgrid, 256>>>(1);
    scatter_kernel<<<scgrid, 256>>>(nullptr, ei, 1);
    gemm_fused<<<gmgrid, 256>>>(nullptr, wl2, wr2, b2, 1);

    // pool + classifier
    zero_kernel<<<64, 256>>>(2);
    pool_kernel<<<plgrid, 256>>>(batch);
    cls_kernel<<<NG, HH>>>(cw, cb, out);
}

// round 10
// speedup vs baseline: 1.3551x; 1.3551x over previous
#include <cuda_runtime.h>
#include <cstdint>

#define NN 50000
#define NE 800000
#define HH 128
#define NG 128

// ---- scratch (device globals; no allocation allowed) ----
__device__ __align__(16) float g_agg[(size_t)NN * HH];   // 25.6 MB
__device__ __align__(16) float g_h1 [(size_t)NN * HH];
__device__ __align__(16) float g_h2 [(size_t)NN * HH];
__device__ float g_deg[NN];
__device__ float g_invdeg[NN];
__device__ __align__(16) float g_pool[NG * HH];
__device__ float g_gcnt[NG];

__device__ __forceinline__ void red_add_v4(float* p, float4 v) {
    asm volatile("red.global.add.v4.f32 [%0], {%1,%2,%3,%4};"
                 :: "l"(p), "f"(v.x), "f"(v.y), "f"(v.z), "f"(v.w)
                 : "memory");
}

__device__ __forceinline__ uint32_t f2tf32(float f) {
    uint32_t r;
    asm("cvt.rna.tf32.f32 %0, %1;" : "=r"(r) : "f"(f));
    return r;
}

// ======================= small kernels =======================
// mode 0: zero agg + deg ; mode 1: zero agg ; mode 2: zero pool + gcnt
__global__ void zero_kernel(int mode) {
    long long i = (long long)blockIdx.x * blockDim.x + threadIdx.x;
    if (mode == 0) {
        if (i < (long long)NN * HH / 4) ((float4*)g_agg)[i] = make_float4(0,0,0,0);
        if (i < NN) g_deg[i] = 0.f;
    } else if (mode == 1) {
        if (i < (long long)NN * HH / 4) ((float4*)g_agg)[i] = make_float4(0,0,0,0);
    } else {
        if (i < NG * HH) g_pool[i] = 0.f;
        if (i < NG)      g_gcnt[i] = 0.f;
    }
}

__global__ void invdeg_kernel() {
    int i = blockIdx.x * blockDim.x + threadIdx.x;
    if (i < NN) g_invdeg[i] = 1.0f / fmaxf(g_deg[i], 1.0f);
}

// one warp per edge: gather feat[src] (float4/lane), vector-reduce into g_agg[dst]
// mode 0: feat = external x, also accumulate degree ; mode 1: feat = g_h1
__global__ void scatter_kernel(const float* __restrict__ xext,
                               const int* __restrict__ ei, int mode) {
    int w = (blockIdx.x * blockDim.x + threadIdx.x) >> 5;
    if (w >= NE) return;
    int lane = threadIdx.x & 31;
    const float* feat = (mode == 0) ? xext : g_h1;
    int src = ei[w];
    int dst = ei[NE + w];
    float4 v = ((const float4*)(feat + (size_t)src * HH))[lane];
    red_add_v4(g_agg + (size_t)dst * HH + (lane << 2), v);
    if (mode == 0 && lane == 0) atomicAdd(&g_deg[dst], 1.0f);
}

// ======================= tf32 mma.sync fused GEMM =======================
// out = relu( (agg*invdeg) @ wl^T + b + xin @ wr^T )
// CTA: 128x128 output, 256 threads, warps in 2x4 grid (64x32 per warp).
// Two K=128 halves accumulate into the same register acc.
// SMEM: As/Bs [128][132] fp32 (pad 4 -> conflict-free frag loads).
#define LDPAD 132
static constexpr int SM_FLOATS = 128 * LDPAD;            // per tile
static constexpr int SM_TOTAL  = 2 * SM_FLOATS * 4;      // 135168 B

__global__ __launch_bounds__(256)
void gemm_mma(const float* __restrict__ xext,
              const float* __restrict__ wl, const float* __restrict__ wr,
              const float* __restrict__ bias, int mode) {
    extern __shared__ float sm[];
    float* As = sm;
    float* Bs = sm + SM_FLOATS;

    const float* xin = (mode == 0) ? xext : g_h1;
    float*       out = (mode == 0) ? g_h1 : g_h2;

    int tid    = threadIdx.x;
    int lane   = tid & 31;
    int wid    = tid >> 5;
    int warp_m = wid >> 2;          // 0..1  (64-row band)
    int warp_n = wid & 3;           // 0..3  (32-col band)
    int m0     = blockIdx.x * 128;

    int grp = lane >> 2;            // 0..7
    int qid = lane & 3;             // 0..3

    float acc[4][4][4];
    #pragma unroll
    for (int mi = 0; mi < 4; ++mi)
        #pragma unroll
        for (int ni = 0; ni < 4; ++ni)
            #pragma unroll
            for (int c = 0; c < 4; ++c) acc[mi][ni][c] = 0.f;

    #pragma unroll 1
    for (int half = 0; half < 2; ++half) {
        const float* A = half ? xin : g_agg;
        const float* W = half ? wr  : wl;

        if (half) __syncthreads();   // protect smem reuse

        // ---- load tiles: 4096 float4 slots, 16 per thread ----
        #pragma unroll
        for (int i = 0; i < 16; ++i) {
            int idx = tid + i * 256;      // 0..4095
            int row = idx >> 5;           // 0..127
            int jj  = idx & 31;           // float4 within row
            int gm  = m0 + row;
            float4 v = make_float4(0.f, 0.f, 0.f, 0.f);
            if (gm < NN) {
                v = *(const float4*)(A + (size_t)gm * HH + (jj << 2));
                if (!half) {
                    float s = g_invdeg[gm];
                    v.x *= s; v.y *= s; v.z *= s; v.w *= s;
                }
            }
            *(float4*)(As + row * LDPAD + (jj << 2)) = v;

            float4 wv = *(const float4*)(W + (size_t)row * HH + (jj << 2));
            *(float4*)(Bs + row * LDPAD + (jj << 2)) = wv;
        }
        __syncthreads();

        // ---- compute: 16 k-steps of 8 ----
        #pragma unroll 4
        for (int ks = 0; ks < 16; ++ks) {
            int k = ks * 8;
            uint32_t a[4][4], b[4][2];
            #pragma unroll
            for (int mi = 0; mi < 4; ++mi) {
                int rb = warp_m * 64 + mi * 16 + grp;
                a[mi][0] = f2tf32(As[rb * LDPAD + k + qid]);
                a[mi][1] = f2tf32(As[(rb + 8) * LDPAD + k + qid]);
                a[mi][2] = f2tf32(As[rb * LDPAD + k + qid + 4]);
                a[mi][3] = f2tf32(As[(rb + 8) * LDPAD + k + qid + 4]);
            }
            #pragma unroll
            for (int ni = 0; ni < 4; ++ni) {
                int n = warp_n * 32 + ni * 8 + grp;
                b[ni][0] = f2tf32(Bs[n * LDPAD + k + qid]);
                b[ni][1] = f2tf32(Bs[n * LDPAD + k + qid + 4]);
            }
            #pragma unroll
            for (int mi = 0; mi < 4; ++mi)
                #pragma unroll
                for (int ni = 0; ni < 4; ++ni)
                    asm volatile(
                        "mma.sync.aligned.m16n8k8.row.col.f32.tf32.tf32.f32 "
                        "{%0,%1,%2,%3}, {%4,%5,%6,%7}, {%8,%9}, {%0,%1,%2,%3};"
                        : "+f"(acc[mi][ni][0]), "+f"(acc[mi][ni][1]),
                          "+f"(acc[mi][ni][2]), "+f"(acc[mi][ni][3])
                        : "r"(a[mi][0]), "r"(a[mi][1]), "r"(a[mi][2]), "r"(a[mi][3]),
                          "r"(b[ni][0]), "r"(b[ni][1]));
        }
    }

    // ---- epilogue: bias + relu ----
    #pragma unroll
    for (int mi = 0; mi < 4; ++mi) {
        int r0 = m0 + warp_m * 64 + mi * 16 + grp;
        #pragma unroll
        for (int ni = 0; ni < 4; ++ni) {
            int col = warp_n * 32 + ni * 8 + qid * 2;
            float bx = bias[col], by = bias[col + 1];
            if (r0 < NN) {
                float2 v;
                v.x = fmaxf(acc[mi][ni][0] + bx, 0.f);
                v.y = fmaxf(acc[mi][ni][1] + by, 0.f);
                *(float2*)(out + (size_t)r0 * HH + col) = v;
            }
            if (r0 + 8 < NN) {
                float2 v;
                v.x = fmaxf(acc[mi][ni][2] + bx, 0.f);
                v.y = fmaxf(acc[mi][ni][3] + by, 0.f);
                *(float2*)(out + (size_t)(r0 + 8) * HH + col) = v;
            }
        }
    }
}

// ======================= pool + classifier =======================
__global__ void pool_kernel(const int* __restrict__ batch) {
    int w = (blockIdx.x * blockDim.x + threadIdx.x) >> 5;
    if (w >= NN) return;
    int lane = threadIdx.x & 31;
    int g = batch[w];
    float4 v = ((const float4*)(g_h2 + (size_t)w * HH))[lane];
    red_add_v4(g_pool + g * HH + (lane << 2), v);
    if (lane == 0) atomicAdd(&g_gcnt[g], 1.0f);
}

__global__ void cls_kernel(const float* __restrict__ cw,
                           const float* __restrict__ cb,
                           float* __restrict__ out) {
    __shared__ float sh[HH];
    int g = blockIdx.x, j = threadIdx.x;
    float inv = 1.0f / fmaxf(g_gcnt[g], 1.0f);
    sh[j] = g_pool[g * HH + j] * inv;
    __syncthreads();
    float acc = 0.f;
    #pragma unroll 8
    for (int k = 0; k < HH; ++k)
        acc += sh[k] * cw[(size_t)j * HH + k];
    out[g * HH + j] = acc + cb[j];
}

// ======================= launch =======================
extern "C" void kernel_launch(void* const* d_in, const int* in_sizes, int n_in,
                              void* d_out, int out_size) {
    const float* x    = (const float*)d_in[0];
    const int*   ei   = (const int*)d_in[1];    // int32 (JAX x64 disabled)
    const int*   batch= (const int*)d_in[2];    // int32
    const float* wl1 = (const float*)d_in[3];
    const float* b1  = (const float*)d_in[4];
    const float* wr1 = (const float*)d_in[5];
    const float* wl2 = (const float*)d_in[6];
    const float* b2  = (const float*)d_in[7];
    const float* wr2 = (const float*)d_in[8];
    const float* cw  = (const float*)d_in[9];
    const float* cb  = (const float*)d_in[10];
    float* out = (float*)d_out;

    cudaFuncSetAttribute(gemm_mma, cudaFuncAttributeMaxDynamicSharedMemorySize, SM_TOTAL);

    const int zgrid  = (NN * HH / 4 + 255) / 256;   // 6250
    const int ngrid  = (NN + 255) / 256;            // 196
    const int scgrid = (NE + 7) / 8;                // 100000 (8 warps/block)
    const int gmgrid = (NN + 127) / 128;            // 391
    const int plgrid = (NN + 7) / 8;                // 6250

    // layer 1 (scatter also accumulates degree)
    zero_kernel<<<zgrid, 256>>>(0);
    scatter_kernel<<<scgrid, 256>>>(x, ei, 0);
    invdeg_kernel<<<ngrid, 256>>>();
    gemm_mma<<<gmgrid, 256, SM_TOTAL>>>(x, wl1, wr1, b1, 0);

    // layer 2
    zero_kernel<<<zgrid, 256>>>(1);
    scatter_kernel<<<scgrid, 256>>>(nullptr, ei, 1);
    gemm_mma<<<gmgrid, 256, SM_TOTAL>>>(nullptr, wl2, wr2, b2, 1);

    // pool + classifier
    zero_kernel<<<64, 256>>>(2);
    pool_kernel<<<plgrid, 256>>>(batch);
    cls_kernel<<<NG, HH>>>(cw, cb, out);
}

// round 11
// speedup vs baseline: 2.1837x; 1.6114x over previous
#include <cuda_runtime.h>
#include <cstdint>

#define NN 50000
#define NE 800000
#define HH 128
#define NG 128
#define NBLK 196   // ceil(NN/256)

// ---- scratch (device globals; no allocation allowed) ----
__device__ __align__(16) float g_agg[(size_t)NN * HH];   // mean-aggregated feats
__device__ __align__(16) float g_h1 [(size_t)NN * HH];
__device__ __align__(16) float g_h2 [(size_t)NN * HH];
__device__ float g_invdeg[NN];
__device__ __align__(16) float g_pool[NG * HH];
__device__ float g_gcnt[NG];
// CSR build
__device__ int g_cnt[NN];
__device__ int g_rowptr[NN + 1];
__device__ int g_cur[NN];
__device__ int g_ssrc[NE];
__device__ int g_bsum[256];

__device__ __forceinline__ void red_add_v4(float* p, float4 v) {
    asm volatile("red.global.add.v4.f32 [%0], {%1,%2,%3,%4};"
                 :: "l"(p), "f"(v.x), "f"(v.y), "f"(v.z), "f"(v.w)
                 : "memory");
}

__device__ __forceinline__ uint32_t f2tf32(float f) {
    uint32_t r;
    asm("cvt.rna.tf32.f32 %0, %1;" : "=r"(r) : "f"(f));
    return r;
}

// ======================= CSR build =======================
__global__ void zero_small_kernel() {
    int i = blockIdx.x * blockDim.x + threadIdx.x;
    if (i < NN) g_cnt[i] = 0;
    if (i < NG * HH) g_pool[i] = 0.f;
    if (i < NG) g_gcnt[i] = 0.f;
}

__global__ void hist_kernel(const int* __restrict__ ei) {
    int e = blockIdx.x * blockDim.x + threadIdx.x;
    if (e < NE) atomicAdd(&g_cnt[ei[NE + e]], 1);
}

// per-block exclusive scan of g_cnt -> g_rowptr (local), block totals -> g_bsum
__global__ void scan1_kernel() {
    __shared__ int sh[256];
    int tx = threadIdx.x;
    int i  = blockIdx.x * 256 + tx;
    int v  = (i < NN) ? g_cnt[i] : 0;
    sh[tx] = v;
    __syncthreads();
    #pragma unroll
    for (int off = 1; off < 256; off <<= 1) {
        int t = (tx >= off) ? sh[tx - off] : 0;
        __syncthreads();
        sh[tx] += t;
        __syncthreads();
    }
    if (i < NN) g_rowptr[i] = sh[tx] - v;            // exclusive within block
    if (tx == 255) g_bsum[blockIdx.x] = sh[255];     // block total
}

__global__ void scan2_kernel() {
    __shared__ int sh[256];
    int tx = threadIdx.x;
    int v  = (tx < NBLK) ? g_bsum[tx] : 0;
    sh[tx] = v;
    __syncthreads();
    #pragma unroll
    for (int off = 1; off < 256; off <<= 1) {
        int t = (tx >= off) ? sh[tx - off] : 0;
        __syncthreads();
        sh[tx] += t;
        __syncthreads();
    }
    g_bsum[tx] = sh[tx] - v;                         // exclusive block offsets
}

__global__ void scan3_kernel() {
    int i = blockIdx.x * blockDim.x + threadIdx.x;
    if (i < NN) {
        int r = g_rowptr[i] + g_bsum[blockIdx.x];
        g_rowptr[i] = r;
        g_cur[i]    = r;
        g_invdeg[i] = 1.0f / fmaxf((float)g_cnt[i], 1.0f);
    }
    if (i == 0) g_rowptr[NN] = NE;
}

__global__ void fill_kernel(const int* __restrict__ ei) {
    int e = blockIdx.x * blockDim.x + threadIdx.x;
    if (e < NE) {
        int dst = ei[NE + e];
        int pos = atomicAdd(&g_cur[dst], 1);
        g_ssrc[pos] = ei[e];
    }
}

// ======================= aggregate (warp per node, CSR gather) =======================
// writes MEAN directly: g_agg[d] = (sum feat[src]) * invdeg[d]
__global__ void agg_kernel(const float* __restrict__ xext, int mode) {
    int w = (blockIdx.x * blockDim.x + threadIdx.x) >> 5;
    if (w >= NN) return;
    int lane = threadIdx.x & 31;
    const float* feat = mode ? g_h1 : xext;
    int beg = g_rowptr[w], end = g_rowptr[w + 1];

    float4 acc = make_float4(0.f, 0.f, 0.f, 0.f);
    int i = beg;
    for (; i + 4 <= end; i += 4) {
        int s0 = g_ssrc[i], s1 = g_ssrc[i+1], s2 = g_ssrc[i+2], s3 = g_ssrc[i+3];
        float4 v0 = ((const float4*)(feat + (size_t)s0 * HH))[lane];
        float4 v1 = ((const float4*)(feat + (size_t)s1 * HH))[lane];
        float4 v2 = ((const float4*)(feat + (size_t)s2 * HH))[lane];
        float4 v3 = ((const float4*)(feat + (size_t)s3 * HH))[lane];
        acc.x += (v0.x + v1.x) + (v2.x + v3.x);
        acc.y += (v0.y + v1.y) + (v2.y + v3.y);
        acc.z += (v0.z + v1.z) + (v2.z + v3.z);
        acc.w += (v0.w + v1.w) + (v2.w + v3.w);
    }
    for (; i < end; ++i) {
        int s = g_ssrc[i];
        float4 v = ((const float4*)(feat + (size_t)s * HH))[lane];
        acc.x += v.x; acc.y += v.y; acc.z += v.z; acc.w += v.w;
    }
    float sc = g_invdeg[w];
    float4 r = make_float4(acc.x * sc, acc.y * sc, acc.z * sc, acc.w * sc);
    ((float4*)(g_agg + (size_t)w * HH))[lane] = r;
}

// ======================= tf32 mma.sync fused GEMM =======================
// out = relu( g_agg @ wl^T + b + xin @ wr^T )   (g_agg is already the mean)
// CTA: 128x128 output, 256 threads, warps 2x4 (64x32 per warp).
// BK=64 chunks -> smem 64KB -> 2 CTAs/SM. tf32 conversion at tile load.
// Unpadded smem with XOR swizzle: col' = col ^ (4*(row&7)); conflict-free for
// both float4 stores and frag loads (row&7 == grp on the frag-load side).
#define BK 64
static constexpr int SM_TOTAL = 2 * 128 * BK * 4;   // 65536 B

__global__ __launch_bounds__(256, 2)
void gemm_mma(const float* __restrict__ xext,
              const float* __restrict__ wl, const float* __restrict__ wr,
              const float* __restrict__ bias, int mode) {
    extern __shared__ uint32_t smu[];
    uint32_t* sA = smu;                 // [128][64] tf32, swizzled
    uint32_t* sB = smu + 128 * BK;      // [128][64] tf32, swizzled (row = out col)

    const float* xin = mode ? g_h1 : xext;
    float*       out = mode ? g_h2 : g_h1;

    int tid    = threadIdx.x;
    int lane   = tid & 31;
    int wid    = tid >> 5;
    int warp_m = wid >> 2;          // 0..1
    int warp_n = wid & 3;           // 0..3
    int m0     = blockIdx.x * 128;
    int grp    = lane >> 2;         // 0..7
    int qid    = lane & 3;          // 0..3

    float acc[4][4][4];
    #pragma unroll
    for (int mi = 0; mi < 4; ++mi)
        #pragma unroll
        for (int ni = 0; ni < 4; ++ni)
            #pragma unroll
            for (int c = 0; c < 4; ++c) acc[mi][ni][c] = 0.f;

    #pragma unroll 1
    for (int half = 0; half < 2; ++half) {
        const float* A = half ? xin : g_agg;
        const float* W = half ? wr  : wl;
        #pragma unroll 1
        for (int kc = 0; kc < HH; kc += BK) {
            if (half | kc) __syncthreads();   // protect smem reuse

            // ---- load chunk: 2048 float4 slots each, 8/thread, cvt to tf32 ----
            #pragma unroll
            for (int i = 0; i < 8; ++i) {
                int idx = tid + i * 256;        // 0..2047
                int row = idx >> 4;             // 0..127
                int jj  = idx & 15;             // float4 within 64-wide row
                int c   = (4 * jj) ^ (4 * (row & 7));
                int gm  = m0 + row;
                float4 v = make_float4(0.f, 0.f, 0.f, 0.f);
                if (gm < NN)
                    v = *(const float4*)(A + (size_t)gm * HH + kc + 4 * jj);
                uint32_t* pa = sA + row * BK + c;
                pa[0] = f2tf32(v.x); pa[1] = f2tf32(v.y);
                pa[2] = f2tf32(v.z); pa[3] = f2tf32(v.w);

                float4 wv = *(const float4*)(W + (size_t)row * HH + kc + 4 * jj);
                uint32_t* pb = sB + row * BK + c;
                pb[0] = f2tf32(wv.x); pb[1] = f2tf32(wv.y);
                pb[2] = f2tf32(wv.z); pb[3] = f2tf32(wv.w);
            }
            __syncthreads();

            // ---- compute: 8 k-steps of 8 ----
            #pragma unroll
            for (int ks = 0; ks < 8; ++ks) {
                int k   = ks * 8;
                int sw0 = (k + qid)     ^ (4 * grp);
                int sw1 = (k + qid + 4) ^ (4 * grp);
                uint32_t a[4][4], b[4][2];
                #pragma unroll
                for (int mi = 0; mi < 4; ++mi) {
                    int rb = warp_m * 64 + mi * 16 + grp;   // rb&7 == grp
                    a[mi][0] = sA[rb * BK + sw0];
                    a[mi][1] = sA[(rb + 8) * BK + sw0];
                    a[mi][2] = sA[rb * BK + sw1];
                    a[mi][3] = sA[(rb + 8) * BK + sw1];
                }
                #pragma unroll
                for (int ni = 0; ni < 4; ++ni) {
                    int n = warp_n * 32 + ni * 8 + grp;     // n&7 == grp
                    b[ni][0] = sB[n * BK + sw0];
                    b[ni][1] = sB[n * BK + sw1];
                }
                #pragma unroll
                for (int mi = 0; mi < 4; ++mi)
                    #pragma unroll
                    for (int ni = 0; ni < 4; ++ni)
                        asm volatile(
                            "mma.sync.aligned.m16n8k8.row.col.f32.tf32.tf32.f32 "
                            "{%0,%1,%2,%3}, {%4,%5,%6,%7}, {%8,%9}, {%0,%1,%2,%3};"
                            : "+f"(acc[mi][ni][0]), "+f"(acc[mi][ni][1]),
                              "+f"(acc[mi][ni][2]), "+f"(acc[mi][ni][3])
                            : "r"(a[mi][0]), "r"(a[mi][1]), "r"(a[mi][2]), "r"(a[mi][3]),
                              "r"(b[ni][0]), "r"(b[ni][1]));
            }
        }
    }

    // ---- epilogue: bias + relu ----
    #pragma unroll
    for (int mi = 0; mi < 4; ++mi) {
        int r0 = m0 + warp_m * 64 + mi * 16 + grp;
        #pragma unroll
        for (int ni = 0; ni < 4; ++ni) {
            int col = warp_n * 32 + ni * 8 + qid * 2;
            float bx = bias[col], by = bias[col + 1];
            if (r0 < NN) {
                float2 v;
                v.x = fmaxf(acc[mi][ni][0] + bx, 0.f);
                v.y = fmaxf(acc[mi][ni][1] + by, 0.f);
                *(float2*)(out + (size_t)r0 * HH + col) = v;
            }
            if (r0 + 8 < NN) {
                float2 v;
                v.x = fmaxf(acc[mi][ni][2] + bx, 0.f);
                v.y = fmaxf(acc[mi][ni][3] + by, 0.f);
                *(float2*)(out + (size_t)(r0 + 8) * HH + col) = v;
            }
        }
    }
}

// ======================= pool + classifier =======================
__global__ void pool_kernel(const int* __restrict__ batch) {
    int w = (blockIdx.x * blockDim.x + threadIdx.x) >> 5;
    if (w >= NN) return;
    int lane = threadIdx.x & 31;
    int g = batch[w];
    float4 v = ((const float4*)(g_h2 + (size_t)w * HH))[lane];
    red_add_v4(g_pool + g * HH + (lane << 2), v);
    if (lane == 0) atomicAdd(&g_gcnt[g], 1.0f);
}

__global__ void cls_kernel(const float* __restrict__ cw,
                           const float* __restrict__ cb,
                           float* __restrict__ out) {
    __shared__ float sh[HH];
    int g = blockIdx.x, j = threadIdx.x;
    float inv = 1.0f / fmaxf(g_gcnt[g], 1.0f);
    sh[j] = g_pool[g * HH + j] * inv;
    __syncthreads();
    float acc = 0.f;
    #pragma unroll 8
    for (int k = 0; k < HH; ++k)
        acc += sh[k] * cw[(size_t)j * HH + k];
    out[g * HH + j] = acc + cb[j];
}

// ======================= launch =======================
extern "C" void kernel_launch(void* const* d_in, const int* in_sizes, int n_in,
                              void* d_out, int out_size) {
    const float* x    = (const float*)d_in[0];
    const int*   ei   = (const int*)d_in[1];    // int32 (JAX x64 disabled)
    const int*   batch= (const int*)d_in[2];    // int32
    const float* wl1 = (const float*)d_in[3];
    const float* b1  = (const float*)d_in[4];
    const float* wr1 = (const float*)d_in[5];
    const float* wl2 = (const float*)d_in[6];
    const float* b2  = (const float*)d_in[7];
    const float* wr2 = (const float*)d_in[8];
    const float* cw  = (const float*)d_in[9];
    const float* cb  = (const float*)d_in[10];
    float* out = (float*)d_out;

    cudaFuncSetAttribute(gemm_mma, cudaFuncAttributeMaxDynamicSharedMemorySize, SM_TOTAL);

    const int egrid  = (NE + 255) / 256;   // 3125
    const int gmgrid = (NN + 127) / 128;   // 391
    const int wgrid  = (NN + 7) / 8;       // 6250 (warp-per-node kernels)

    // CSR build (edge list shared by both layers)
    zero_small_kernel<<<NBLK, 256>>>();
    hist_kernel<<<egrid, 256>>>(ei);
    scan1_kernel<<<NBLK, 256>>>();
    scan2_kernel<<<1, 256>>>();
    scan3_kernel<<<NBLK, 256>>>();
    fill_kernel<<<egrid, 256>>>(ei);

    // layer 1
    agg_kernel<<<wgrid, 256>>>(x, 0);
    gemm_mma<<<gmgrid, 256, SM_TOTAL>>>(x, wl1, wr1, b1, 0);

    // layer 2
    agg_kernel<<<wgrid, 256>>>(nullptr, 1);
    gemm_mma<<<gmgrid, 256, SM_TOTAL>>>(nullptr, wl2, wr2, b2, 1);

    // pool + classifier
    pool_kernel<<<wgrid, 256>>>(batch);
    cls_kernel<<<NG, HH>>>(cw, cb, out);
}

// round 12
// speedup vs baseline: 2.7172x; 1.2443x over previous
#include <cuda_runtime.h>
#include <cuda_fp16.h>
#include <cstdint>

#define NN 50000
#define NE 800000
#define HH 128
#define NG 128
#define NBLK 196   // ceil(NN/256)

// ---- scratch (device globals; no allocation allowed) ----
__device__ __align__(16) __half g_x16 [(size_t)NN * HH];  // fp16 copy of x
__device__ __align__(16) __half g_agg16[(size_t)NN * HH]; // mean-aggregated (fp16)
__device__ __align__(16) __half g_h116[(size_t)NN * HH];
__device__ __align__(16) __half g_h216[(size_t)NN * HH];
__device__ float g_invdeg[NN];
__device__ __align__(16) float g_pool[NG * HH];
__device__ float g_gcnt[NG];
// CSR build
__device__ int g_cnt[NN];
__device__ int g_rowptr[NN + 1];
__device__ int g_cur[NN];
__device__ int g_ssrc[NE];
__device__ int g_bsum[256];

__device__ __forceinline__ void red_add_v4(float* p, float4 v) {
    asm volatile("red.global.add.v4.f32 [%0], {%1,%2,%3,%4};"
                 :: "l"(p), "f"(v.x), "f"(v.y), "f"(v.z), "f"(v.w)
                 : "memory");
}

__device__ __forceinline__ uint32_t smem_u32(const void* p) {
    uint32_t a;
    asm("{ .reg .u64 t; cvta.to.shared.u64 t, %1; cvt.u32.u64 %0, t; }"
        : "=r"(a) : "l"(p));
    return a;
}

// ======================= fp16 convert =======================
__global__ void x2h_kernel(const float* __restrict__ x) {
    int i = blockIdx.x * blockDim.x + threadIdx.x;     // one uint4 (8 halves) each
    if (i >= NN * HH / 8) return;
    float4 a = ((const float4*)x)[2 * i];
    float4 b = ((const float4*)x)[2 * i + 1];
    __half2 h0 = __floats2half2_rn(a.x, a.y);
    __half2 h1 = __floats2half2_rn(a.z, a.w);
    __half2 h2 = __floats2half2_rn(b.x, b.y);
    __half2 h3 = __floats2half2_rn(b.z, b.w);
    uint4 o;
    o.x = *(uint32_t*)&h0; o.y = *(uint32_t*)&h1;
    o.z = *(uint32_t*)&h2; o.w = *(uint32_t*)&h3;
    ((uint4*)g_x16)[i] = o;
}

// ======================= CSR build =======================
__global__ void zero_small_kernel() {
    int i = blockIdx.x * blockDim.x + threadIdx.x;
    if (i < NN) g_cnt[i] = 0;
    if (i < NG * HH) g_pool[i] = 0.f;
    if (i < NG) g_gcnt[i] = 0.f;
}

__global__ void hist_kernel(const int* __restrict__ ei) {
    int e = blockIdx.x * blockDim.x + threadIdx.x;
    if (e < NE) atomicAdd(&g_cnt[ei[NE + e]], 1);
}

__global__ void scan1_kernel() {
    __shared__ int sh[256];
    int tx = threadIdx.x;
    int i  = blockIdx.x * 256 + tx;
    int v  = (i < NN) ? g_cnt[i] : 0;
    sh[tx] = v;
    __syncthreads();
    #pragma unroll
    for (int off = 1; off < 256; off <<= 1) {
        int t = (tx >= off) ? sh[tx - off] : 0;
        __syncthreads();
        sh[tx] += t;
        __syncthreads();
    }
    if (i < NN) g_rowptr[i] = sh[tx] - v;
    if (tx == 255) g_bsum[blockIdx.x] = sh[255];
}

__global__ void scan2_kernel() {
    __shared__ int sh[256];
    int tx = threadIdx.x;
    int v  = (tx < NBLK) ? g_bsum[tx] : 0;
    sh[tx] = v;
    __syncthreads();
    #pragma unroll
    for (int off = 1; off < 256; off <<= 1) {
        int t = (tx >= off) ? sh[tx - off] : 0;
        __syncthreads();
        sh[tx] += t;
        __syncthreads();
    }
    g_bsum[tx] = sh[tx] - v;
}

__global__ void scan3_kernel() {
    int i = blockIdx.x * blockDim.x + threadIdx.x;
    if (i < NN) {
        int r = g_rowptr[i] + g_bsum[blockIdx.x];
        g_rowptr[i] = r;
        g_cur[i]    = r;
        g_invdeg[i] = 1.0f / fmaxf((float)g_cnt[i], 1.0f);
    }
    if (i == 0) g_rowptr[NN] = NE;
}

__global__ void fill_kernel(const int* __restrict__ ei) {
    int e = blockIdx.x * blockDim.x + threadIdx.x;
    if (e < NE) {
        int dst = ei[NE + e];
        int pos = atomicAdd(&g_cur[dst], 1);
        g_ssrc[pos] = ei[e];
    }
}

// ======================= aggregate (warp per node, fp16 CSR gather) =======================
// g_agg16[d] = fp16( (sum_src feat16[src]) * invdeg[d] ), fp32 accumulation
__global__ void agg_kernel(int mode) {
    int w = (blockIdx.x * blockDim.x + threadIdx.x) >> 5;
    if (w >= NN) return;
    int lane = threadIdx.x & 31;
    const __half* feat = mode ? g_h116 : g_x16;
    int beg = g_rowptr[w], end = g_rowptr[w + 1];

    float4 acc = make_float4(0.f, 0.f, 0.f, 0.f);
    int i = beg;
    for (; i + 4 <= end; i += 4) {
        int s0 = g_ssrc[i], s1 = g_ssrc[i+1], s2 = g_ssrc[i+2], s3 = g_ssrc[i+3];
        uint2 u0 = ((const uint2*)(feat + (size_t)s0 * HH))[lane];
        uint2 u1 = ((const uint2*)(feat + (size_t)s1 * HH))[lane];
        uint2 u2 = ((const uint2*)(feat + (size_t)s2 * HH))[lane];
        uint2 u3 = ((const uint2*)(feat + (size_t)s3 * HH))[lane];
        float2 a0 = __half22float2(*(__half2*)&u0.x), b0 = __half22float2(*(__half2*)&u0.y);
        float2 a1 = __half22float2(*(__half2*)&u1.x), b1 = __half22float2(*(__half2*)&u1.y);
        float2 a2 = __half22float2(*(__half2*)&u2.x), b2 = __half22float2(*(__half2*)&u2.y);
        float2 a3 = __half22float2(*(__half2*)&u3.x), b3 = __half22float2(*(__half2*)&u3.y);
        acc.x += (a0.x + a1.x) + (a2.x + a3.x);
        acc.y += (a0.y + a1.y) + (a2.y + a3.y);
        acc.z += (b0.x + b1.x) + (b2.x + b3.x);
        acc.w += (b0.y + b1.y) + (b2.y + b3.y);
    }
    for (; i < end; ++i) {
        int s = g_ssrc[i];
        uint2 u = ((const uint2*)(feat + (size_t)s * HH))[lane];
        float2 a = __half22float2(*(__half2*)&u.x), b = __half22float2(*(__half2*)&u.y);
        acc.x += a.x; acc.y += a.y; acc.z += b.x; acc.w += b.y;
    }
    float sc = g_invdeg[w];
    __half2 o0 = __floats2half2_rn(acc.x * sc, acc.y * sc);
    __half2 o1 = __floats2half2_rn(acc.z * sc, acc.w * sc);
    uint2 o;
    o.x = *(uint32_t*)&o0; o.y = *(uint32_t*)&o1;
    ((uint2*)(g_agg16 + (size_t)w * HH))[lane] = o;
}

// ======================= fp16 mma.sync fused GEMM =======================
// out16 = fp16(relu( agg16 @ wl^T + b + xin16 @ wr^T ))
// CTA 128x128, 256 threads, warps 2x4 (64x32/warp), full K=128 resident.
// smem: sA/sB [128 rows][256 B] fp16, 16B-chunk XOR swizzle (chunk ^= row&7).
// ldmatrix m8n8 (non-trans) for both A (rows=m) and B (rows=n), k-major both.
static constexpr int SM_TOTAL = 2 * 128 * 256;   // 65536 B

__global__ __launch_bounds__(256, 2)
void gemm_mma(const float* __restrict__ wl, const float* __restrict__ wr,
              const float* __restrict__ bias, int mode) {
    extern __shared__ char smc[];
    char* sA = smc;
    char* sB = smc + 128 * 256;
    uint32_t sAu = smem_u32(sA);
    uint32_t sBu = smem_u32(sB);

    const __half* xin16 = mode ? g_h116 : g_x16;
    __half*       out16 = mode ? g_h216 : g_h116;

    int tid    = threadIdx.x;
    int lane   = tid & 31;
    int wid    = tid >> 5;
    int warp_m = wid >> 2;          // 0..1
    int warp_n = wid & 3;           // 0..3
    int m0     = blockIdx.x * 128;
    int grp    = lane >> 2;         // 0..7
    int qid    = lane & 3;          // 0..3

    float acc[4][4][4];
    #pragma unroll
    for (int mi = 0; mi < 4; ++mi)
        #pragma unroll
        for (int ni = 0; ni < 4; ++ni)
            #pragma unroll
            for (int c = 0; c < 4; ++c) acc[mi][ni][c] = 0.f;

    #pragma unroll 1
    for (int ph = 0; ph < 2; ++ph) {
        const __half* A16 = ph ? xin16 : g_agg16;
        const float*  W   = ph ? wr    : wl;

        if (ph) __syncthreads();   // protect smem reuse

        // ---- load: 2048 16B-chunks each (8 per thread); B converts fp32->fp16 ----
        #pragma unroll
        for (int i = 0; i < 8; ++i) {
            int idx = tid + i * 256;        // 0..2047
            int row = idx >> 4;             // 0..127
            int ch  = idx & 15;             // 16B chunk within 256B row
            int sc  = ch ^ (row & 7);
            int gm  = m0 + row;

            uint4 av = make_uint4(0, 0, 0, 0);
            if (gm < NN)
                av = *(const uint4*)((const char*)A16 + (size_t)gm * 256 + ch * 16);
            *(uint4*)(sA + row * 256 + sc * 16) = av;

            float4 w0 = *(const float4*)(W + (size_t)row * HH + ch * 8);
            float4 w1 = *(const float4*)(W + (size_t)row * HH + ch * 8 + 4);
            __half2 h0 = __floats2half2_rn(w0.x, w0.y);
            __half2 h1 = __floats2half2_rn(w0.z, w0.w);
            __half2 h2 = __floats2half2_rn(w1.x, w1.y);
            __half2 h3 = __floats2half2_rn(w1.z, w1.w);
            uint4 bv;
            bv.x = *(uint32_t*)&h0; bv.y = *(uint32_t*)&h1;
            bv.z = *(uint32_t*)&h2; bv.w = *(uint32_t*)&h3;
            *(uint4*)(sB + row * 256 + sc * 16) = bv;
        }
        __syncthreads();

        // ---- compute: 8 k-steps of 16 ----
        #pragma unroll
        for (int ks = 0; ks < 8; ++ks) {
            int kk = ks * 16;               // in halves
            uint32_t af[4][4], bf[4][2];
            #pragma unroll
            for (int mi = 0; mi < 4; ++mi) {
                int rb = warp_m * 64 + mi * 16;
                int lr = rb + (lane & 15);
                int lc = (kk >> 3) + (lane >> 4);
                uint32_t addr = sAu + lr * 256 + ((lc ^ (lr & 7)) << 4);
                asm volatile("ldmatrix.sync.aligned.m8n8.x4.shared.b16 "
                             "{%0,%1,%2,%3}, [%4];"
                             : "=r"(af[mi][0]), "=r"(af[mi][1]),
                               "=r"(af[mi][2]), "=r"(af[mi][3])
                             : "r"(addr));
            }
            #pragma unroll
            for (int ni = 0; ni < 4; ++ni) {
                int nb = warp_n * 32 + ni * 8;
                int ln = nb + (lane & 7);
                int lc = (kk >> 3) + ((lane >> 3) & 1);
                uint32_t addr = sBu + ln * 256 + ((lc ^ (ln & 7)) << 4);
                asm volatile("ldmatrix.sync.aligned.m8n8.x2.shared.b16 "
                             "{%0,%1}, [%2];"
                             : "=r"(bf[ni][0]), "=r"(bf[ni][1])
                             : "r"(addr));
            }
            #pragma unroll
            for (int mi = 0; mi < 4; ++mi)
                #pragma unroll
                for (int ni = 0; ni < 4; ++ni)
                    asm volatile(
                        "mma.sync.aligned.m16n8k16.row.col.f32.f16.f16.f32 "
                        "{%0,%1,%2,%3}, {%4,%5,%6,%7}, {%8,%9}, {%0,%1,%2,%3};"
                        : "+f"(acc[mi][ni][0]), "+f"(acc[mi][ni][1]),
                          "+f"(acc[mi][ni][2]), "+f"(acc[mi][ni][3])
                        : "r"(af[mi][0]), "r"(af[mi][1]),
                          "r"(af[mi][2]), "r"(af[mi][3]),
                          "r"(bf[ni][0]), "r"(bf[ni][1]));
        }
    }

    // ---- epilogue: bias + relu -> fp16 ----
    #pragma unroll
    for (int mi = 0; mi < 4; ++mi) {
        int r0 = m0 + warp_m * 64 + mi * 16 + grp;
        #pragma unroll
        for (int ni = 0; ni < 4; ++ni) {
            int col = warp_n * 32 + ni * 8 + qid * 2;
            float bx = bias[col], by = bias[col + 1];
            if (r0 < NN) {
                __half2 v = __floats2half2_rn(fmaxf(acc[mi][ni][0] + bx, 0.f),
                                              fmaxf(acc[mi][ni][1] + by, 0.f));
                *(__half2*)(out16 + (size_t)r0 * HH + col) = v;
            }
            if (r0 + 8 < NN) {
                __half2 v = __floats2half2_rn(fmaxf(acc[mi][ni][2] + bx, 0.f),
                                              fmaxf(acc[mi][ni][3] + by, 0.f));
                *(__half2*)(out16 + (size_t)(r0 + 8) * HH + col) = v;
            }
        }
    }
}

// ======================= pool + classifier =======================
__global__ void pool_kernel(const int* __restrict__ batch) {
    int w = (blockIdx.x * blockDim.x + threadIdx.x) >> 5;
    if (w >= NN) return;
    int lane = threadIdx.x & 31;
    int g = batch[w];
    uint2 u = ((const uint2*)(g_h216 + (size_t)w * HH))[lane];
    float2 a = __half22float2(*(__half2*)&u.x);
    float2 b = __half22float2(*(__half2*)&u.y);
    red_add_v4(g_pool + g * HH + (lane << 2), make_float4(a.x, a.y, b.x, b.y));
    if (lane == 0) atomicAdd(&g_gcnt[g], 1.0f);
}

__global__ void cls_kernel(const float* __restrict__ cw,
                           const float* __restrict__ cb,
                           float* __restrict__ out) {
    __shared__ float sh[HH];
    int g = blockIdx.x, j = threadIdx.x;
    float inv = 1.0f / fmaxf(g_gcnt[g], 1.0f);
    sh[j] = g_pool[g * HH + j] * inv;
    __syncthreads();
    float acc = 0.f;
    #pragma unroll 8
    for (int k = 0; k < HH; ++k)
        acc += sh[k] * cw[(size_t)j * HH + k];
    out[g * HH + j] = acc + cb[j];
}

// ======================= launch =======================
extern "C" void kernel_launch(void* const* d_in, const int* in_sizes, int n_in,
                              void* d_out, int out_size) {
    const float* x    = (const float*)d_in[0];
    const int*   ei   = (const int*)d_in[1];    // int32 (JAX x64 disabled)
    const int*   batch= (const int*)d_in[2];    // int32
    const float* wl1 = (const float*)d_in[3];
    const float* b1  = (const float*)d_in[4];
    const float* wr1 = (const float*)d_in[5];
    const float* wl2 = (const float*)d_in[6];
    const float* b2  = (const float*)d_in[7];
    const float* wr2 = (const float*)d_in[8];
    const float* cw  = (const float*)d_in[9];
    const float* cb  = (const float*)d_in[10];
    float* out = (float*)d_out;

    cudaFuncSetAttribute(gemm_mma, cudaFuncAttributeMaxDynamicSharedMemorySize, SM_TOTAL);

    const int egrid  = (NE + 255) / 256;          // 3125
    const int gmgrid = (NN + 127) / 128;          // 391
    const int wgrid  = (NN + 7) / 8;              // 6250
    const int cvgrid = (NN * HH / 8 + 255) / 256; // 3125

    // fp16 copy of x + CSR build (edge list shared by both layers)
    x2h_kernel<<<cvgrid, 256>>>(x);
    zero_small_kernel<<<NBLK, 256>>>();
    hist_kernel<<<egrid, 256>>>(ei);
    scan1_kernel<<<NBLK, 256>>>();
    scan2_kernel<<<1, 256>>>();
    scan3_kernel<<<NBLK, 256>>>();
    fill_kernel<<<egrid, 256>>>(ei);

    // layer 1
    agg_kernel<<<wgrid, 256>>>(0);
    gemm_mma<<<gmgrid, 256, SM_TOTAL>>>(wl1, wr1, b1, 0);

    // layer 2
    agg_kernel<<<wgrid, 256>>>(1);
    gemm_mma<<<gmgrid, 256, SM_TOTAL>>>(wl2, wr2, b2, 1);

    // pool + classifier
    pool_kernel<<<wgrid, 256>>>(batch);
    cls_kernel<<<NG, HH>>>(cw, cb, out);
}

// round 14
// speedup vs baseline: 2.9510x; 1.0860x over previous
#include <cuda_runtime.h>
#include <cuda_fp16.h>
#include <cstdint>

#define NN 50000
#define NE 800000
#define HH 128
#define NG 128
#define NBLK 196   // ceil(NN/256)

// ---- scratch (device globals; no allocation allowed) ----
__device__ __align__(16) __half g_x16 [(size_t)NN * HH];  // fp16 copy of x
__device__ __align__(16) __half g_agg16[(size_t)NN * HH]; // mean-aggregated (fp16)
__device__ __align__(16) __half g_h116[(size_t)NN * HH];
__device__ __align__(16) __half g_w16[4 * HH * HH];       // wl1,wr1,wl2,wr2 fp16
__device__ float g_invdeg[NN];
__device__ __align__(16) float g_pool[NG * HH];
__device__ float g_gcnt[NG];
// CSR build
__device__ int g_cnt[NN];
__device__ int g_rowptr[NN + 1];
__device__ int g_cur[NN];
__device__ int g_ssrc[NE];
__device__ int g_bsum[256];

__device__ __forceinline__ void red_add_v2(float* p, float2 v) {
    asm volatile("red.global.add.v2.f32 [%0], {%1,%2};"
                 :: "l"(p), "f"(v.x), "f"(v.y) : "memory");
}

__device__ __forceinline__ uint32_t smem_u32(const void* p) {
    uint32_t a;
    asm("{ .reg .u64 t; cvta.to.shared.u64 t, %1; cvt.u32.u64 %0, t; }"
        : "=r"(a) : "l"(p));
    return a;
}

__device__ __forceinline__ uint4 f8_to_h8(float4 a, float4 b) {
    __half2 h0 = __floats2half2_rn(a.x, a.y);
    __half2 h1 = __floats2half2_rn(a.z, a.w);
    __half2 h2 = __floats2half2_rn(b.x, b.y);
    __half2 h3 = __floats2half2_rn(b.z, b.w);
    uint4 o;
    o.x = *(uint32_t*)&h0; o.y = *(uint32_t*)&h1;
    o.z = *(uint32_t*)&h2; o.w = *(uint32_t*)&h3;
    return o;
}

// ======================= prep: x->fp16, W->fp16, zeros =======================
// NOTE: zeroes g_gcnt here; it is ACCUMULATED later in scan23_kernel. Keeping
// zero and accumulate in separate kernels makes kernel_launch idempotent.
__global__ void prep_kernel(const float* __restrict__ x,
                            const float* __restrict__ wl1, const float* __restrict__ wr1,
                            const float* __restrict__ wl2, const float* __restrict__ wr2) {
    int i = blockIdx.x * blockDim.x + threadIdx.x;   // one uint4 (8 halves) per thread
    if (i < NN * HH / 8) {
        float4 a = ((const float4*)x)[2 * i];
        float4 b = ((const float4*)x)[2 * i + 1];
        ((uint4*)g_x16)[i] = f8_to_h8(a, b);
    }
    if (i < 4 * HH * HH / 8) {                       // weights: 8192 chunks
        int mat = i >> 11;
        int j   = i & 2047;
        const float* W = (mat == 0) ? wl1 : (mat == 1) ? wr1 : (mat == 2) ? wl2 : wr2;
        float4 a = ((const float4*)W)[2 * j];
        float4 b = ((const float4*)W)[2 * j + 1];
        ((uint4*)(g_w16 + (size_t)mat * HH * HH))[j] = f8_to_h8(a, b);
    }
    if (i < NN) g_cnt[i] = 0;
    if (i < NG * HH) g_pool[i] = 0.f;
    if (i < NG) g_gcnt[i] = 0.f;
}

// ======================= CSR build =======================
__global__ void hist_kernel(const int* __restrict__ ei) {
    int e = blockIdx.x * blockDim.x + threadIdx.x;
    if (e < NE) atomicAdd(&g_cnt[ei[NE + e]], 1);
}

__global__ void scan1_kernel() {
    __shared__ int sh[256];
    int tx = threadIdx.x;
    int i  = blockIdx.x * 256 + tx;
    int v  = (i < NN) ? g_cnt[i] : 0;
    sh[tx] = v;
    __syncthreads();
    #pragma unroll
    for (int off = 1; off < 256; off <<= 1) {
        int t = (tx >= off) ? sh[tx - off] : 0;
        __syncthreads();
        sh[tx] += t;
        __syncthreads();
    }
    if (i < NN) g_rowptr[i] = sh[tx] - v;            // exclusive within block
    if (tx == 255) g_bsum[blockIdx.x] = sh[255];     // block total
}

// each block computes its own prefix over g_bsum, finalizes rowptr/cur/invdeg,
// and accumulates per-graph node counts (exact int fp32 adds: deterministic).
__global__ void scan23_kernel(const int* __restrict__ batch) {
    __shared__ int sh[256];
    int tx = threadIdx.x;
    int b  = blockIdx.x;
    int v  = (tx < b) ? g_bsum[tx] : 0;              // sum of totals before block b
    sh[tx] = v;
    __syncthreads();
    #pragma unroll
    for (int off = 128; off > 0; off >>= 1) {
        if (tx < off) sh[tx] += sh[tx + off];
        __syncthreads();
    }
    int offset = sh[0];
    int i = b * 256 + tx;
    if (i < NN) {
        int r = g_rowptr[i] + offset;
        g_rowptr[i] = r;
        g_cur[i]    = r;
        g_invdeg[i] = 1.0f / fmaxf((float)g_cnt[i], 1.0f);
        atomicAdd(&g_gcnt[batch[i]], 1.0f);
    }
    if (i == 0) g_rowptr[NN] = NE;
}

__global__ void fill_kernel(const int* __restrict__ ei) {
    int e = blockIdx.x * blockDim.x + threadIdx.x;
    if (e < NE) {
        int dst = ei[NE + e];
        int pos = atomicAdd(&g_cur[dst], 1);
        g_ssrc[pos] = ei[e];
    }
}

// ======================= aggregate (warp per node, fp16 CSR gather) =======================
__global__ void agg_kernel(int mode) {
    int w = (blockIdx.x * blockDim.x + threadIdx.x) >> 5;
    if (w >= NN) return;
    int lane = threadIdx.x & 31;
    const __half* feat = mode ? g_h116 : g_x16;
    int beg = g_rowptr[w], end = g_rowptr[w + 1];

    float4 acc = make_float4(0.f, 0.f, 0.f, 0.f);
    int i = beg;
    for (; i + 4 <= end; i += 4) {
        int s0 = g_ssrc[i], s1 = g_ssrc[i+1], s2 = g_ssrc[i+2], s3 = g_ssrc[i+3];
        uint2 u0 = ((const uint2*)(feat + (size_t)s0 * HH))[lane];
        uint2 u1 = ((const uint2*)(feat + (size_t)s1 * HH))[lane];
        uint2 u2 = ((const uint2*)(feat + (size_t)s2 * HH))[lane];
        uint2 u3 = ((const uint2*)(feat + (size_t)s3 * HH))[lane];
        float2 a0 = __half22float2(*(__half2*)&u0.x), b0 = __half22float2(*(__half2*)&u0.y);
        float2 a1 = __half22float2(*(__half2*)&u1.x), b1 = __half22float2(*(__half2*)&u1.y);
        float2 a2 = __half22float2(*(__half2*)&u2.x), b2 = __half22float2(*(__half2*)&u2.y);
        float2 a3 = __half22float2(*(__half2*)&u3.x), b3 = __half22float2(*(__half2*)&u3.y);
        acc.x += (a0.x + a1.x) + (a2.x + a3.x);
        acc.y += (a0.y + a1.y) + (a2.y + a3.y);
        acc.z += (b0.x + b1.x) + (b2.x + b3.x);
        acc.w += (b0.y + b1.y) + (b2.y + b3.y);
    }
    for (; i < end; ++i) {
        int s = g_ssrc[i];
        uint2 u = ((const uint2*)(feat + (size_t)s * HH))[lane];
        float2 a = __half22float2(*(__half2*)&u.x), b = __half22float2(*(__half2*)&u.y);
        acc.x += a.x; acc.y += a.y; acc.z += b.x; acc.w += b.y;
    }
    float sc = g_invdeg[w];
    __half2 o0 = __floats2half2_rn(acc.x * sc, acc.y * sc);
    __half2 o1 = __floats2half2_rn(acc.z * sc, acc.w * sc);
    uint2 o;
    o.x = *(uint32_t*)&o0; o.y = *(uint32_t*)&o1;
    ((uint2*)(g_agg16 + (size_t)w * HH))[lane] = o;
}

// ======================= fp16 mma.sync fused GEMM =======================
// mode 0: h1 = fp16(relu(agg@wl1^T + b1 + x@wr1^T))
// mode 1: pool[g] += relu(agg@wl2^T + b2 + h1@wr2^T)   (red.add, no h2 store)
static constexpr int SM_TOTAL = 2 * 128 * 256;   // 65536 B

__global__ __launch_bounds__(256, 2)
void gemm_mma(const float* __restrict__ bias, const int* __restrict__ batch, int mode) {
    extern __shared__ char smc[];
    char* sA = smc;
    char* sB = smc + 128 * 256;
    uint32_t sAu = smem_u32(sA);
    uint32_t sBu = smem_u32(sB);

    const __half* xin16 = mode ? g_h116 : g_x16;

    int tid    = threadIdx.x;
    int lane   = tid & 31;
    int wid    = tid >> 5;
    int warp_m = wid >> 2;          // 0..1
    int warp_n = wid & 3;           // 0..3
    int m0     = blockIdx.x * 128;
    int grp    = lane >> 2;         // 0..7
    int qid    = lane & 3;          // 0..3

    float acc[4][4][4];
    #pragma unroll
    for (int mi = 0; mi < 4; ++mi)
        #pragma unroll
        for (int ni = 0; ni < 4; ++ni)
            #pragma unroll
            for (int c = 0; c < 4; ++c) acc[mi][ni][c] = 0.f;

    #pragma unroll 1
    for (int ph = 0; ph < 2; ++ph) {
        const __half* A16 = ph ? xin16 : g_agg16;
        const __half* W16 = g_w16 + (size_t)(mode * 2 + ph) * HH * HH;

        if (ph) __syncthreads();   // protect smem reuse

        // ---- load: 2048 16B-chunks each (8 per thread), both fp16 ----
        #pragma unroll
        for (int i = 0; i < 8; ++i) {
            int idx = tid + i * 256;        // 0..2047
            int row = idx >> 4;             // 0..127
            int ch  = idx & 15;             // 16B chunk within 256B row
            int sc  = ch ^ (row & 7);
            int gm  = m0 + row;

            uint4 av = make_uint4(0, 0, 0, 0);
            if (gm < NN)
                av = *(const uint4*)((const char*)A16 + (size_t)gm * 256 + ch * 16);
            *(uint4*)(sA + row * 256 + sc * 16) = av;

            uint4 bv = *(const uint4*)((const char*)W16 + (size_t)row * 256 + ch * 16);
            *(uint4*)(sB + row * 256 + sc * 16) = bv;
        }
        __syncthreads();

        // ---- compute: 8 k-steps of 16 ----
        #pragma unroll
        for (int ks = 0; ks < 8; ++ks) {
            int kk = ks * 16;               // in halves
            uint32_t af[4][4], bf[4][2];
            #pragma unroll
            for (int mi = 0; mi < 4; ++mi) {
                int rb = warp_m * 64 + mi * 16;
                int lr = rb + (lane & 15);
                int lc = (kk >> 3) + (lane >> 4);
                uint32_t addr = sAu + lr * 256 + ((lc ^ (lr & 7)) << 4);
                asm volatile("ldmatrix.sync.aligned.m8n8.x4.shared.b16 "
                             "{%0,%1,%2,%3}, [%4];"
                             : "=r"(af[mi][0]), "=r"(af[mi][1]),
                               "=r"(af[mi][2]), "=r"(af[mi][3])
                             : "r"(addr));
            }
            #pragma unroll
            for (int ni = 0; ni < 4; ++ni) {
                int nb = warp_n * 32 + ni * 8;
                int ln = nb + (lane & 7);
                int lc = (kk >> 3) + ((lane >> 3) & 1);
                uint32_t addr = sBu + ln * 256 + ((lc ^ (ln & 7)) << 4);
                asm volatile("ldmatrix.sync.aligned.m8n8.x2.shared.b16 "
                             "{%0,%1}, [%2];"
                             : "=r"(bf[ni][0]), "=r"(bf[ni][1])
                             : "r"(addr));
            }
            #pragma unroll
            for (int mi = 0; mi < 4; ++mi)
                #pragma unroll
                for (int ni = 0; ni < 4; ++ni)
                    asm volatile(
                        "mma.sync.aligned.m16n8k16.row.col.f32.f16.f16.f32 "
                        "{%0,%1,%2,%3}, {%4,%5,%6,%7}, {%8,%9}, {%0,%1,%2,%3};"
                        : "+f"(acc[mi][ni][0]), "+f"(acc[mi][ni][1]),
                          "+f"(acc[mi][ni][2]), "+f"(acc[mi][ni][3])
                        : "r"(af[mi][0]), "r"(af[mi][1]),
                          "r"(af[mi][2]), "r"(af[mi][3]),
                          "r"(bf[ni][0]), "r"(bf[ni][1]));
        }
    }

    // ---- epilogue ----
    if (mode == 0) {
        #pragma unroll
        for (int mi = 0; mi < 4; ++mi) {
            int r0 = m0 + warp_m * 64 + mi * 16 + grp;
            #pragma unroll
            for (int ni = 0; ni < 4; ++ni) {
                int col = warp_n * 32 + ni * 8 + qid * 2;
                float bx = bias[col], by = bias[col + 1];
                if (r0 < NN) {
                    __half2 v = __floats2half2_rn(fmaxf(acc[mi][ni][0] + bx, 0.f),
                                                  fmaxf(acc[mi][ni][1] + by, 0.f));
                    *(__half2*)(g_h116 + (size_t)r0 * HH + col) = v;
                }
                if (r0 + 8 < NN) {
                    __half2 v = __floats2half2_rn(fmaxf(acc[mi][ni][2] + bx, 0.f),
                                                  fmaxf(acc[mi][ni][3] + by, 0.f));
                    *(__half2*)(g_h116 + (size_t)(r0 + 8) * HH + col) = v;
                }
            }
        }
    } else {
        // fused pool: red.add relu(h2) into g_pool[batch[row]]
        #pragma unroll
        for (int mi = 0; mi < 4; ++mi) {
            int r0 = m0 + warp_m * 64 + mi * 16 + grp;
            int gA = (r0 < NN)     ? batch[r0]     : 0;
            int gB = (r0 + 8 < NN) ? batch[r0 + 8] : 0;
            #pragma unroll
            for (int ni = 0; ni < 4; ++ni) {
                int col = warp_n * 32 + ni * 8 + qid * 2;
                float bx = bias[col], by = bias[col + 1];
                if (r0 < NN) {
                    float2 v = make_float2(fmaxf(acc[mi][ni][0] + bx, 0.f),
                                           fmaxf(acc[mi][ni][1] + by, 0.f));
                    red_add_v2(g_pool + gA * HH + col, v);
                }
                if (r0 + 8 < NN) {
                    float2 v = make_float2(fmaxf(acc[mi][ni][2] + bx, 0.f),
                                           fmaxf(acc[mi][ni][3] + by, 0.f));
                    red_add_v2(g_pool + gB * HH + col, v);
                }
            }
        }
    }
}

// ======================= classifier =======================
__global__ void cls_kernel(const float* __restrict__ cw,
                           const float* __restrict__ cb,
                           float* __restrict__ out) {
    __shared__ float sh[HH];
    int g = blockIdx.x, j = threadIdx.x;
    float inv = 1.0f / fmaxf(g_gcnt[g], 1.0f);
    sh[j] = g_pool[g * HH + j] * inv;
    __syncthreads();
    float acc = 0.f;
    #pragma unroll 8
    for (int k = 0; k < HH; ++k)
        acc += sh[k] * cw[(size_t)j * HH + k];
    out[g * HH + j] = acc + cb[j];
}

// ======================= launch =======================
extern "C" void kernel_launch(void* const* d_in, const int* in_sizes, int n_in,
                              void* d_out, int out_size) {
    const float* x    = (const float*)d_in[0];
    const int*   ei   = (const int*)d_in[1];    // int32 (JAX x64 disabled)
    const int*   batch= (const int*)d_in[2];    // int32
    const float* wl1 = (const float*)d_in[3];
    const float* b1  = (const float*)d_in[4];
    const float* wr1 = (const float*)d_in[5];
    const float* wl2 = (const float*)d_in[6];
    const float* b2  = (const float*)d_in[7];
    const float* wr2 = (const float*)d_in[8];
    const float* cw  = (const float*)d_in[9];
    const float* cb  = (const float*)d_in[10];
    float* out = (float*)d_out;

    cudaFuncSetAttribute(gemm_mma, cudaFuncAttributeMaxDynamicSharedMemorySize, SM_TOTAL);

    const int egrid  = (NE + 255) / 256;          // 3125
    const int gmgrid = (NN + 127) / 128;          // 391
    const int wgrid  = (NN + 7) / 8;              // 6250
    const int cvgrid = (NN * HH / 8 + 255) / 256; // 3125

    // prep (x->fp16, W->fp16, zero cnt/pool/gcnt) + CSR build (+gcnt accumulate)
    prep_kernel<<<cvgrid, 256>>>(x, wl1, wr1, wl2, wr2);
    hist_kernel<<<egrid, 256>>>(ei);
    scan1_kernel<<<NBLK, 256>>>();
    scan23_kernel<<<NBLK, 256>>>(batch);
    fill_kernel<<<egrid, 256>>>(ei);

    // layer 1
    agg_kernel<<<wgrid, 256>>>(0);
    gemm_mma<<<gmgrid, 256, SM_TOTAL>>>(b1, batch, 0);

    // layer 2 (pool fused into gemm epilogue)
    agg_kernel<<<wgrid, 256>>>(1);
    gemm_mma<<<gmgrid, 256, SM_TOTAL>>>(b2, batch, 1);

    // classifier
    cls_kernel<<<NG, HH>>>(cw, cb, out);
}

// round 16
// speedup vs baseline: 3.4553x; 1.1709x over previous
#include <cuda_runtime.h>
#include <cuda_fp16.h>
#include <cstdint>

#define NN 50000
#define NE 800000
#define HH 128
#define NG 128
#define NBLK 196   // ceil(NN/256)

// ---- scratch (device globals; no allocation allowed) ----
__device__ __align__(16) __half g_x16 [(size_t)NN * HH];  // fp16 copy of x
__device__ __align__(16) __half g_agg16[(size_t)NN * HH]; // mean-aggregated (fp16)
__device__ __align__(16) __half g_h116[(size_t)NN * HH];
__device__ __align__(16) __half g_w16[4 * HH * HH];       // wl1,wr1,wl2,wr2 fp16
__device__ float g_invdeg[NN];
__device__ __align__(16) float g_pool[NG * HH];
__device__ float g_gcnt[NG];
// CSR build
__device__ int g_cnt[NN];
__device__ int g_rowptr[NN + 1];
__device__ int g_cur[NN];
__device__ int g_ssrc[NE];
__device__ int g_bsum[256];

__device__ __forceinline__ void red_add_v2(float* p, float2 v) {
    asm volatile("red.global.add.v2.f32 [%0], {%1,%2};"
                 :: "l"(p), "f"(v.x), "f"(v.y) : "memory");
}

__device__ __forceinline__ uint32_t smem_u32(const void* p) {
    uint32_t a;
    asm("{ .reg .u64 t; cvta.to.shared.u64 t, %1; cvt.u32.u64 %0, t; }"
        : "=r"(a) : "l"(p));
    return a;
}

__device__ __forceinline__ uint4 f8_to_h8(float4 a, float4 b) {
    __half2 h0 = __floats2half2_rn(a.x, a.y);
    __half2 h1 = __floats2half2_rn(a.z, a.w);
    __half2 h2 = __floats2half2_rn(b.x, b.y);
    __half2 h3 = __floats2half2_rn(b.z, b.w);
    uint4 o;
    o.x = *(uint32_t*)&h0; o.y = *(uint32_t*)&h1;
    o.z = *(uint32_t*)&h2; o.w = *(uint32_t*)&h3;
    return o;
}

// ======================= prep: x->fp16, W->fp16, zeros =======================
__global__ void prep_kernel(const float* __restrict__ x,
                            const float* __restrict__ wl1, const float* __restrict__ wr1,
                            const float* __restrict__ wl2, const float* __restrict__ wr2) {
    int i = blockIdx.x * blockDim.x + threadIdx.x;   // one uint4 (8 halves) per thread
    if (i < NN * HH / 8) {
        float4 a = ((const float4*)x)[2 * i];
        float4 b = ((const float4*)x)[2 * i + 1];
        ((uint4*)g_x16)[i] = f8_to_h8(a, b);
    }
    if (i < 4 * HH * HH / 8) {                       // weights: 8192 chunks
        int mat = i >> 11;
        int j   = i & 2047;
        const float* W = (mat == 0) ? wl1 : (mat == 1) ? wr1 : (mat == 2) ? wl2 : wr2;
        float4 a = ((const float4*)W)[2 * j];
        float4 b = ((const float4*)W)[2 * j + 1];
        ((uint4*)(g_w16 + (size_t)mat * HH * HH))[j] = f8_to_h8(a, b);
    }
    if (i < NN) g_cnt[i] = 0;
    if (i < NG * HH) g_pool[i] = 0.f;
    if (i < NG) g_gcnt[i] = 0.f;
}

// ======================= CSR build =======================
__global__ void hist_kernel(const int* __restrict__ ei) {
    int e = blockIdx.x * blockDim.x + threadIdx.x;
    if (e < NE) atomicAdd(&g_cnt[ei[NE + e]], 1);
}

__global__ void scan1_kernel() {
    __shared__ int sh[256];
    int tx = threadIdx.x;
    int i  = blockIdx.x * 256 + tx;
    int v  = (i < NN) ? g_cnt[i] : 0;
    sh[tx] = v;
    __syncthreads();
    #pragma unroll
    for (int off = 1; off < 256; off <<= 1) {
        int t = (tx >= off) ? sh[tx - off] : 0;
        __syncthreads();
        sh[tx] += t;
        __syncthreads();
    }
    if (i < NN) g_rowptr[i] = sh[tx] - v;            // exclusive within block
    if (tx == 255) g_bsum[blockIdx.x] = sh[255];     // block total
}

// each block: prefix over g_bsum, finalize rowptr/cur/invdeg, and accumulate
// per-graph node counts via a BLOCK-LOCAL smem histogram (batch is sorted, so
// each block hits only a few bins; global atomics drop 50000 -> ~500).
__global__ void scan23_kernel(const int* __restrict__ batch) {
    __shared__ int sh[256];
    __shared__ int hist[NG];
    int tx = threadIdx.x;
    int b  = blockIdx.x;
    if (tx < NG) hist[tx] = 0;
    int v  = (tx < b) ? g_bsum[tx] : 0;              // sum of totals before block b
    sh[tx] = v;
    __syncthreads();
    #pragma unroll
    for (int off = 128; off > 0; off >>= 1) {
        if (tx < off) sh[tx] += sh[tx + off];
        __syncthreads();
    }
    int offset = sh[0];
    int i = b * 256 + tx;
    if (i < NN) {
        int r = g_rowptr[i] + offset;
        g_rowptr[i] = r;
        g_cur[i]    = r;
        g_invdeg[i] = 1.0f / fmaxf((float)g_cnt[i], 1.0f);
        atomicAdd(&hist[batch[i]], 1);
    }
    if (i == 0) g_rowptr[NN] = NE;
    __syncthreads();
    if (tx < NG) {
        int h = hist[tx];
        if (h) atomicAdd(&g_gcnt[tx], (float)h);     // exact int fp32: deterministic
    }
}

__global__ void fill_kernel(const int* __restrict__ ei) {
    int e = blockIdx.x * blockDim.x + threadIdx.x;
    if (e < NE) {
        int dst = ei[NE + e];
        int pos = atomicAdd(&g_cur[dst], 1);
        g_ssrc[pos] = ei[e];
    }
}

// ======================= aggregate (warp per node, fp16 CSR gather) =======================
__global__ void agg_kernel(int mode) {
    int w = (blockIdx.x * blockDim.x + threadIdx.x) >> 5;
    if (w >= NN) return;
    int lane = threadIdx.x & 31;
    const __half* feat = mode ? g_h116 : g_x16;
    int beg = g_rowptr[w], end = g_rowptr[w + 1];

    float4 acc = make_float4(0.f, 0.f, 0.f, 0.f);
    int i = beg;
    for (; i + 4 <= end; i += 4) {
        int s0 = g_ssrc[i], s1 = g_ssrc[i+1], s2 = g_ssrc[i+2], s3 = g_ssrc[i+3];
        uint2 u0 = ((const uint2*)(feat + (size_t)s0 * HH))[lane];
        uint2 u1 = ((const uint2*)(feat + (size_t)s1 * HH))[lane];
        uint2 u2 = ((const uint2*)(feat + (size_t)s2 * HH))[lane];
        uint2 u3 = ((const uint2*)(feat + (size_t)s3 * HH))[lane];
        float2 a0 = __half22float2(*(__half2*)&u0.x), b0 = __half22float2(*(__half2*)&u0.y);
        float2 a1 = __half22float2(*(__half2*)&u1.x), b1 = __half22float2(*(__half2*)&u1.y);
        float2 a2 = __half22float2(*(__half2*)&u2.x), b2 = __half22float2(*(__half2*)&u2.y);
        float2 a3 = __half22float2(*(__half2*)&u3.x), b3 = __half22float2(*(__half2*)&u3.y);
        acc.x += (a0.x + a1.x) + (a2.x + a3.x);
        acc.y += (a0.y + a1.y) + (a2.y + a3.y);
        acc.z += (b0.x + b1.x) + (b2.x + b3.x);
        acc.w += (b0.y + b1.y) + (b2.y + b3.y);
    }
    for (; i < end; ++i) {
        int s = g_ssrc[i];
        uint2 u = ((const uint2*)(feat + (size_t)s * HH))[lane];
        float2 a = __half22float2(*(__half2*)&u.x), b = __half22float2(*(__half2*)&u.y);
        acc.x += a.x; acc.y += a.y; acc.z += b.x; acc.w += b.y;
    }
    float sc = g_invdeg[w];
    __half2 o0 = __floats2half2_rn(acc.x * sc, acc.y * sc);
    __half2 o1 = __floats2half2_rn(acc.z * sc, acc.w * sc);
    uint2 o;
    o.x = *(uint32_t*)&o0; o.y = *(uint32_t*)&o1;
    ((uint2*)(g_agg16 + (size_t)w * HH))[lane] = o;
}

// ======================= fp16 mma.sync fused GEMM =======================
// mode 0: h1 = fp16(relu(agg@wl1^T + b1 + x@wr1^T))
// mode 1: pool[g] += relu(agg@wl2^T + b2 + h1@wr2^T)   (red.add, no h2 store)
static constexpr int SM_TOTAL = 2 * 128 * 256;   // 65536 B

__global__ __launch_bounds__(256, 2)
void gemm_mma(const float* __restrict__ bias, const int* __restrict__ batch, int mode) {
    extern __shared__ char smc[];
    char* sA = smc;
    char* sB = smc + 128 * 256;
    uint32_t sAu = smem_u32(sA);
    uint32_t sBu = smem_u32(sB);

    const __half* xin16 = mode ? g_h116 : g_x16;

    int tid    = threadIdx.x;
    int lane   = tid & 31;
    int wid    = tid >> 5;
    int warp_m = wid >> 2;          // 0..1
    int warp_n = wid & 3;           // 0..3
    int m0     = blockIdx.x * 128;
    int grp    = lane >> 2;         // 0..7
    int qid    = lane & 3;          // 0..3

    float acc[4][4][4];
    #pragma unroll
    for (int mi = 0; mi < 4; ++mi)
        #pragma unroll
        for (int ni = 0; ni < 4; ++ni)
            #pragma unroll
            for (int c = 0; c < 4; ++c) acc[mi][ni][c] = 0.f;

    #pragma unroll 1
    for (int ph = 0; ph < 2; ++ph) {
        const __half* A16 = ph ? xin16 : g_agg16;
        const __half* W16 = g_w16 + (size_t)(mode * 2 + ph) * HH * HH;

        if (ph) __syncthreads();   // protect smem reuse

        // ---- load: 2048 16B-chunks each (8 per thread), both fp16 ----
        #pragma unroll
        for (int i = 0; i < 8; ++i) {
            int idx = tid + i * 256;        // 0..2047
            int row = idx >> 4;             // 0..127
            int ch  = idx & 15;             // 16B chunk within 256B row
            int sc  = ch ^ (row & 7);
            int gm  = m0 + row;

            uint4 av = make_uint4(0, 0, 0, 0);
            if (gm < NN)
                av = *(const uint4*)((const char*)A16 + (size_t)gm * 256 + ch * 16);
            *(uint4*)(sA + row * 256 + sc * 16) = av;

            uint4 bv = *(const uint4*)((const char*)W16 + (size_t)row * 256 + ch * 16);
            *(uint4*)(sB + row * 256 + sc * 16) = bv;
        }
        __syncthreads();

        // ---- compute: 8 k-steps of 16 ----
        #pragma unroll
        for (int ks = 0; ks < 8; ++ks) {
            int kk = ks * 16;               // in halves
            uint32_t af[4][4], bf[4][2];
            #pragma unroll
            for (int mi = 0; mi < 4; ++mi) {
                int rb = warp_m * 64 + mi * 16;
                int lr = rb + (lane & 15);
                int lc = (kk >> 3) + (lane >> 4);
                uint32_t addr = sAu + lr * 256 + ((lc ^ (lr & 7)) << 4);
                asm volatile("ldmatrix.sync.aligned.m8n8.x4.shared.b16 "
                             "{%0,%1,%2,%3}, [%4];"
                             : "=r"(af[mi][0]), "=r"(af[mi][1]),
                               "=r"(af[mi][2]), "=r"(af[mi][3])
                             : "r"(addr));
            }
            #pragma unroll
            for (int ni = 0; ni < 4; ++ni) {
                int nb = warp_n * 32 + ni * 8;
                int ln = nb + (lane & 7);
                int lc = (kk >> 3) + ((lane >> 3) & 1);
                uint32_t addr = sBu + ln * 256 + ((lc ^ (ln & 7)) << 4);
                asm volatile("ldmatrix.sync.aligned.m8n8.x2.shared.b16 "
                             "{%0,%1}, [%2];"
                             : "=r"(bf[ni][0]), "=r"(bf[ni][1])
                             : "r"(addr));
            }
            #pragma unroll
            for (int mi = 0; mi < 4; ++mi)
                #pragma unroll
                for (int ni = 0; ni < 4; ++ni)
                    asm volatile(
                        "mma.sync.aligned.m16n8k16.row.col.f32.f16.f16.f32 "
                        "{%0,%1,%2,%3}, {%4,%5,%6,%7}, {%8,%9}, {%0,%1,%2,%3};"
                        : "+f"(acc[mi][ni][0]), "+f"(acc[mi][ni][1]),
                          "+f"(acc[mi][ni][2]), "+f"(acc[mi][ni][3])
                        : "r"(af[mi][0]), "r"(af[mi][1]),
                          "r"(af[mi][2]), "r"(af[mi][3]),
                          "r"(bf[ni][0]), "r"(bf[ni][1]));
        }
    }

    // ---- epilogue ----
    if (mode == 0) {
        #pragma unroll
        for (int mi = 0; mi < 4; ++mi) {
            int r0 = m0 + warp_m * 64 + mi * 16 + grp;
            #pragma unroll
            for (int ni = 0; ni < 4; ++ni) {
                int col = warp_n * 32 + ni * 8 + qid * 2;
                float bx = bias[col], by = bias[col + 1];
                if (r0 < NN) {
                    __half2 v = __floats2half2_rn(fmaxf(acc[mi][ni][0] + bx, 0.f),
                                                  fmaxf(acc[mi][ni][1] + by, 0.f));
                    *(__half2*)(g_h116 + (size_t)r0 * HH + col) = v;
                }
                if (r0 + 8 < NN) {
                    __half2 v = __floats2half2_rn(fmaxf(acc[mi][ni][2] + bx, 0.f),
                                                  fmaxf(acc[mi][ni][3] + by, 0.f));
                    *(__half2*)(g_h116 + (size_t)(r0 + 8) * HH + col) = v;
                }
            }
        }
    } else {
        // fused pool: red.add relu(h2) into g_pool[batch[row]]
        #pragma unroll
        for (int mi = 0; mi < 4; ++mi) {
            int r0 = m0 + warp_m * 64 + mi * 16 + grp;
            int gA = (r0 < NN)     ? batch[r0]     : 0;
            int gB = (r0 + 8 < NN) ? batch[r0 + 8] : 0;
            #pragma unroll
            for (int ni = 0; ni < 4; ++ni) {
                int col = warp_n * 32 + ni * 8 + qid * 2;
                float bx = bias[col], by = bias[col + 1];
                if (r0 < NN) {
                    float2 v = make_float2(fmaxf(acc[mi][ni][0] + bx, 0.f),
                                           fmaxf(acc[mi][ni][1] + by, 0.f));
                    red_add_v2(g_pool + gA * HH + col, v);
                }
                if (r0 + 8 < NN) {
                    float2 v = make_float2(fmaxf(acc[mi][ni][2] + bx, 0.f),
                                           fmaxf(acc[mi][ni][3] + by, 0.f));
                    red_add_v2(g_pool + gB * HH + col, v);
                }
            }
        }
    }
}

// ======================= classifier =======================
__global__ void cls_kernel(const float* __restrict__ cw,
                           const float* __restrict__ cb,
                           float* __restrict__ out) {
    __shared__ float sh[HH];
    int g = blockIdx.x, j = threadIdx.x;
    float inv = 1.0f / fmaxf(g_gcnt[g], 1.0f);
    sh[j] = g_pool[g * HH + j] * inv;
    __syncthreads();
    float acc = 0.f;
    #pragma unroll 8
    for (int k = 0; k < HH; ++k)
        acc += sh[k] * cw[(size_t)j * HH + k];
    out[g * HH + j] = acc + cb[j];
}

// ======================= launch =======================
extern "C" void kernel_launch(void* const* d_in, const int* in_sizes, int n_in,
                              void* d_out, int out_size) {
    const float* x    = (const float*)d_in[0];
    const int*   ei   = (const int*)d_in[1];    // int32 (JAX x64 disabled)
    const int*   batch= (const int*)d_in[2];    // int32
    const float* wl1 = (const float*)d_in[3];
    const float* b1  = (const float*)d_in[4];
    const float* wr1 = (const float*)d_in[5];
    const float* wl2 = (const float*)d_in[6];
    const float* b2  = (const float*)d_in[7];
    const float* wr2 = (const float*)d_in[8];
    const float* cw  = (const float*)d_in[9];
    const float* cb  = (const float*)d_in[10];
    float* out = (float*)d_out;

    cudaFuncSetAttribute(gemm_mma, cudaFuncAttributeMaxDynamicSharedMemorySize, SM_TOTAL);

    const int egrid  = (NE + 255) / 256;          // 3125
    const int gmgrid = (NN + 127) / 128;          // 391
    const int wgrid  = (NN + 7) / 8;              // 6250
    const int cvgrid = (NN * HH / 8 + 255) / 256; // 3125

    // prep (x->fp16, W->fp16, zero cnt/pool/gcnt) + CSR build (+gcnt accumulate)
    prep_kernel<<<cvgrid, 256>>>(x, wl1, wr1, wl2, wr2);
    hist_kernel<<<egrid, 256>>>(ei);
    scan1_kernel<<<NBLK, 256>>>();
    scan23_kernel<<<NBLK, 256>>>(batch);
    fill_kernel<<<egrid, 256>>>(ei);

    // layer 1
    agg_kernel<<<wgrid, 256>>>(0);
    gemm_mma<<<gmgrid, 256, SM_TOTAL>>>(b1, batch, 0);

    // layer 2 (pool fused into gemm epilogue)
    agg_kernel<<<wgrid, 256>>>(1);
    gemm_mma<<<gmgrid, 256, SM_TOTAL>>>(b2, batch, 1);

    // classifier
    cls_kernel<<<NG, HH>>>(cw, cb, out);
}

// round 17
// speedup vs baseline: 3.5698x; 1.0331x over previous
#include <cuda_runtime.h>
#include <cuda_fp16.h>
#include <cstdint>

#define NN 50000
#define NE 800000
#define HH 128
#define NG 128
#define NBLK 196   // ceil(NN/256)

// ---- scratch (device globals; no allocation allowed) ----
__device__ __align__(16) __half g_x16 [(size_t)NN * HH];  // fp16 copy of x
__device__ __align__(16) __half g_agg16[(size_t)NN * HH]; // mean-aggregated (fp16)
__device__ __align__(16) __half g_h116[(size_t)NN * HH];
__device__ __align__(16) __half g_w16[4 * HH * HH];       // wl1,wr1,wl2,wr2 fp16
__device__ float g_invdeg[NN];
__device__ __align__(16) float g_pool[NG * HH];
__device__ float g_gcnt[NG];
// CSR build
__device__ int g_cnt[NN];
__device__ int g_rowptr[NN + 1];
__device__ int g_cur[NN];
__device__ int g_ssrc[NE];
__device__ int g_bsum[256];

__device__ __forceinline__ void red_add_v2(float* p, float2 v) {
    asm volatile("red.global.add.v2.f32 [%0], {%1,%2};"
                 :: "l"(p), "f"(v.x), "f"(v.y) : "memory");
}

__device__ __forceinline__ uint32_t smem_u32(const void* p) {
    uint32_t a;
    asm("{ .reg .u64 t; cvta.to.shared.u64 t, %1; cvt.u32.u64 %0, t; }"
        : "=r"(a) : "l"(p));
    return a;
}

__device__ __forceinline__ void cp16(uint32_t dst, const void* src, bool valid) {
    int sz = valid ? 16 : 0;
    asm volatile("cp.async.cg.shared.global [%0], [%1], 16, %2;"
                 :: "r"(dst), "l"(src), "r"(sz) : "memory");
}

__device__ __forceinline__ uint4 f8_to_h8(float4 a, float4 b) {
    __half2 h0 = __floats2half2_rn(a.x, a.y);
    __half2 h1 = __floats2half2_rn(a.z, a.w);
    __half2 h2 = __floats2half2_rn(b.x, b.y);
    __half2 h3 = __floats2half2_rn(b.z, b.w);
    uint4 o;
    o.x = *(uint32_t*)&h0; o.y = *(uint32_t*)&h1;
    o.z = *(uint32_t*)&h2; o.w = *(uint32_t*)&h3;
    return o;
}

// ============ prep: x->fp16, W->fp16, zeros, AND edge histogram ============
// grid is 3125*256 = 800000 threads = NE exactly; hist rides along.
__global__ void prep_kernel(const float* __restrict__ x,
                            const int* __restrict__ ei,
                            const float* __restrict__ wl1, const float* __restrict__ wr1,
                            const float* __restrict__ wl2, const float* __restrict__ wr2) {
    int i = blockIdx.x * blockDim.x + threadIdx.x;   // one uint4 (8 halves) per thread
    if (i < NN) g_cnt[i] = 0;
    if (i < NG * HH) g_pool[i] = 0.f;
    if (i < NG) g_gcnt[i] = 0.f;
    if (i < NN * HH / 8) {
        float4 a = ((const float4*)x)[2 * i];
        float4 b = ((const float4*)x)[2 * i + 1];
        ((uint4*)g_x16)[i] = f8_to_h8(a, b);
    }
    if (i < 4 * HH * HH / 8) {                       // weights: 8192 chunks
        int mat = i >> 11;
        int j   = i & 2047;
        const float* W = (mat == 0) ? wl1 : (mat == 1) ? wr1 : (mat == 2) ? wl2 : wr2;
        float4 a = ((const float4*)W)[2 * j];
        float4 b = ((const float4*)W)[2 * j + 1];
        ((uint4*)(g_w16 + (size_t)mat * HH * HH))[j] = f8_to_h8(a, b);
    }
}

// hist must start after prep zeroed g_cnt -> separate tiny kernel would race;
// instead hist is its own pass over edges fused with NOTHING that reads g_cnt.
__global__ void hist_kernel(const int* __restrict__ ei) {
    int e = blockIdx.x * blockDim.x + threadIdx.x;
    if (e < NE) atomicAdd(&g_cnt[ei[NE + e]], 1);
}

// ======================= CSR build =======================
__global__ void scan1_kernel() {
    __shared__ int sh[256];
    int tx = threadIdx.x;
    int i  = blockIdx.x * 256 + tx;
    int v  = (i < NN) ? g_cnt[i] : 0;
    sh[tx] = v;
    __syncthreads();
    #pragma unroll
    for (int off = 1; off < 256; off <<= 1) {
        int t = (tx >= off) ? sh[tx - off] : 0;
        __syncthreads();
        sh[tx] += t;
        __syncthreads();
    }
    if (i < NN) g_rowptr[i] = sh[tx] - v;            // exclusive within block
    if (tx == 255) g_bsum[blockIdx.x] = sh[255];     // block total
}

__global__ void scan23_kernel(const int* __restrict__ batch) {
    __shared__ int sh[256];
    __shared__ int hist[NG];
    int tx = threadIdx.x;
    int b  = blockIdx.x;
    if (tx < NG) hist[tx] = 0;
    int v  = (tx < b) ? g_bsum[tx] : 0;              // sum of totals before block b
    sh[tx] = v;
    __syncthreads();
    #pragma unroll
    for (int off = 128; off > 0; off >>= 1) {
        if (tx < off) sh[tx] += sh[tx + off];
        __syncthreads();
    }
    int offset = sh[0];
    int i = b * 256 + tx;
    if (i < NN) {
        int r = g_rowptr[i] + offset;
        g_rowptr[i] = r;
        g_cur[i]    = r;
        g_invdeg[i] = 1.0f / fmaxf((float)g_cnt[i], 1.0f);
        atomicAdd(&hist[batch[i]], 1);
    }
    if (i == 0) g_rowptr[NN] = NE;
    __syncthreads();
    if (tx < NG) {
        int h = hist[tx];
        if (h) atomicAdd(&g_gcnt[tx], (float)h);     // exact int fp32: deterministic
    }
}

__global__ void fill_kernel(const int* __restrict__ ei) {
    int e = blockIdx.x * blockDim.x + threadIdx.x;
    if (e < NE) {
        int dst = ei[NE + e];
        int pos = atomicAdd(&g_cur[dst], 1);
        g_ssrc[pos] = ei[e];
    }
}

// ============ aggregate (warp per node, fp16 CSR gather) ============
__global__ void agg_kernel(int mode) {
    int w = (blockIdx.x * blockDim.x + threadIdx.x) >> 5;
    if (w >= NN) return;
    int lane = threadIdx.x & 31;
    const __half* feat = mode ? g_h116 : g_x16;
    int beg = g_rowptr[w], end = g_rowptr[w + 1];

    float4 acc = make_float4(0.f, 0.f, 0.f, 0.f);
    int i = beg;
    for (; i + 4 <= end; i += 4) {
        int s0 = g_ssrc[i], s1 = g_ssrc[i+1], s2 = g_ssrc[i+2], s3 = g_ssrc[i+3];
        uint2 u0 = ((const uint2*)(feat + (size_t)s0 * HH))[lane];
        uint2 u1 = ((const uint2*)(feat + (size_t)s1 * HH))[lane];
        uint2 u2 = ((const uint2*)(feat + (size_t)s2 * HH))[lane];
        uint2 u3 = ((const uint2*)(feat + (size_t)s3 * HH))[lane];
        float2 a0 = __half22float2(*(__half2*)&u0.x), b0 = __half22float2(*(__half2*)&u0.y);
        float2 a1 = __half22float2(*(__half2*)&u1.x), b1 = __half22float2(*(__half2*)&u1.y);
        float2 a2 = __half22float2(*(__half2*)&u2.x), b2 = __half22float2(*(__half2*)&u2.y);
        float2 a3 = __half22float2(*(__half2*)&u3.x), b3 = __half22float2(*(__half2*)&u3.y);
        acc.x += (a0.x + a1.x) + (a2.x + a3.x);
        acc.y += (a0.y + a1.y) + (a2.y + a3.y);
        acc.z += (b0.x + b1.x) + (b2.x + b3.x);
        acc.w += (b0.y + b1.y) + (b2.y + b3.y);
    }
    for (; i < end; ++i) {
        int s = g_ssrc[i];
        uint2 u = ((const uint2*)(feat + (size_t)s * HH))[lane];
        float2 a = __half22float2(*(__half2*)&u.x), b = __half22float2(*(__half2*)&u.y);
        acc.x += a.x; acc.y += a.y; acc.z += b.x; acc.w += b.y;
    }
    float sc = g_invdeg[w];
    __half2 o0 = __floats2half2_rn(acc.x * sc, acc.y * sc);
    __half2 o1 = __floats2half2_rn(acc.z * sc, acc.w * sc);
    uint2 o;
    o.x = *(uint32_t*)&o0; o.y = *(uint32_t*)&o1;
    ((uint2*)(g_agg16 + (size_t)w * HH))[lane] = o;
}

// ============ fp16 mma.sync fused GEMM, cp.async 4-stage pipeline ============
// mode 0: h1 = fp16(relu(agg@wl1^T + b1 + x@wr1^T))
// mode 1: pool[g] += relu(agg@wl2^T + b2 + h1@wr2^T)
// Stages: s = phase*2 + khalf. Each stage = A-half(16KB)+B-half(16KB) in
// buf[s&1] (2 x 32KB = 64KB). Load(s+1) overlaps compute(s).
static constexpr int SM_TOTAL = 2 * 32768;   // 65536 B

__global__ __launch_bounds__(256, 2)
void gemm_mma(const float* __restrict__ bias, const int* __restrict__ batch, int mode) {
    extern __shared__ char smc[];
    uint32_t sbase = smem_u32(smc);

    const __half* xin16 = mode ? g_h116 : g_x16;

    int tid    = threadIdx.x;
    int lane   = tid & 31;
    int wid    = tid >> 5;
    int warp_m = wid >> 2;          // 0..1
    int warp_n = wid & 3;           // 0..3
    int m0     = blockIdx.x * 128;
    int grp    = lane >> 2;         // 0..7
    int qid    = lane & 3;          // 0..3

    float acc[4][4][4];
    #pragma unroll
    for (int mi = 0; mi < 4; ++mi)
        #pragma unroll
        for (int ni = 0; ni < 4; ++ni)
            #pragma unroll
            for (int c = 0; c < 4; ++c) acc[mi][ni][c] = 0.f;

    // ---- stage loader: 1024 A-chunks + 1024 B-chunks (4+4 per thread) ----
    auto load_stage = [&](int s) {
        const __half* A16 = (s < 2) ? g_agg16 : xin16;
        const __half* W16 = g_w16 + (size_t)(mode * 2 + (s >> 1)) * HH * HH;
        int kc = (s & 1) * 128;                  // byte offset within 256B row
        uint32_t buf = sbase + (uint32_t)(s & 1) * 32768;
        #pragma unroll
        for (int i = 0; i < 4; ++i) {
            int idx = tid + i * 256;             // 0..1023
            int row = idx >> 3;                  // 0..127
            int ch  = idx & 7;                   // 16B chunk within 128B half-row
            int sc  = ch ^ (row & 7);
            int gm  = m0 + row;
            bool valid = gm < NN;
            const char* srcA = (const char*)A16 + (size_t)(valid ? gm : 0) * 256 + kc + ch * 16;
            cp16(buf + row * 128 + sc * 16, srcA, valid);
            const char* srcB = (const char*)W16 + (size_t)row * 256 + kc + ch * 16;
            cp16(buf + 16384 + row * 128 + sc * 16, srcB, true);
        }
        asm volatile("cp.async.commit_group;" ::: "memory");
    };

    load_stage(0);
    #pragma unroll 1
    for (int s = 0; s < 4; ++s) {
        if (s < 3) {
            load_stage(s + 1);
            asm volatile("cp.async.wait_group 1;" ::: "memory");
        } else {
            asm volatile("cp.async.wait_group 0;" ::: "memory");
        }
        __syncthreads();

        uint32_t sAu = sbase + (uint32_t)(s & 1) * 32768;
        uint32_t sBu = sAu + 16384;
        #pragma unroll
        for (int ks = 0; ks < 4; ++ks) {
            int kk = ks * 16;                    // stage-local k in halves
            uint32_t af[4][4], bf[4][2];
            #pragma unroll
            for (int mi = 0; mi < 4; ++mi) {
                int rb = warp_m * 64 + mi * 16;
                int lr = rb + (lane & 15);
                int lc = (kk >> 3) + (lane >> 4);          // 0..7
                uint32_t addr = sAu + lr * 128 + ((lc ^ (lr & 7)) << 4);
                asm volatile("ldmatrix.sync.aligned.m8n8.x4.shared.b16 "
                             "{%0,%1,%2,%3}, [%4];"
                             : "=r"(af[mi][0]), "=r"(af[mi][1]),
                               "=r"(af[mi][2]), "=r"(af[mi][3])
                             : "r"(addr));
            }
            #pragma unroll
            for (int ni = 0; ni < 4; ++ni) {
                int nb = warp_n * 32 + ni * 8;
                int ln = nb + (lane & 7);
                int lc = (kk >> 3) + ((lane >> 3) & 1);    // 0..7
                uint32_t addr = sBu + ln * 128 + ((lc ^ (ln & 7)) << 4);
                asm volatile("ldmatrix.sync.aligned.m8n8.x2.shared.b16 "
                             "{%0,%1}, [%2];"
                             : "=r"(bf[ni][0]), "=r"(bf[ni][1])
                             : "r"(addr));
            }
            #pragma unroll
            for (int mi = 0; mi < 4; ++mi)
                #pragma unroll
                for (int ni = 0; ni < 4; ++ni)
                    asm volatile(
                        "mma.sync.aligned.m16n8k16.row.col.f32.f16.f16.f32 "
                        "{%0,%1,%2,%3}, {%4,%5,%6,%7}, {%8,%9}, {%0,%1,%2,%3};"
                        : "+f"(acc[mi][ni][0]), "+f"(acc[mi][ni][1]),
                          "+f"(acc[mi][ni][2]), "+f"(acc[mi][ni][3])
                        : "r"(af[mi][0]), "r"(af[mi][1]),
                          "r"(af[mi][2]), "r"(af[mi][3]),
                          "r"(bf[ni][0]), "r"(bf[ni][1]));
        }
        __syncthreads();
    }

    // ---- epilogue ----
    if (mode == 0) {
        #pragma unroll
        for (int mi = 0; mi < 4; ++mi) {
            int r0 = m0 + warp_m * 64 + mi * 16 + grp;
            #pragma unroll
            for (int ni = 0; ni < 4; ++ni) {
                int col = warp_n * 32 + ni * 8 + qid * 2;
                float bx = bias[col], by = bias[col + 1];
                if (r0 < NN) {
                    __half2 v = __floats2half2_rn(fmaxf(acc[mi][ni][0] + bx, 0.f),
                                                  fmaxf(acc[mi][ni][1] + by, 0.f));
                    *(__half2*)(g_h116 + (size_t)r0 * HH + col) = v;
                }
                if (r0 + 8 < NN) {
                    __half2 v = __floats2half2_rn(fmaxf(acc[mi][ni][2] + bx, 0.f),
                                                  fmaxf(acc[mi][ni][3] + by, 0.f));
                    *(__half2*)(g_h116 + (size_t)(r0 + 8) * HH + col) = v;
                }
            }
        }
    } else {
        #pragma unroll
        for (int mi = 0; mi < 4; ++mi) {
            int r0 = m0 + warp_m * 64 + mi * 16 + grp;
            int gA = (r0 < NN)     ? batch[r0]     : 0;
            int gB = (r0 + 8 < NN) ? batch[r0 + 8] : 0;
            #pragma unroll
            for (int ni = 0; ni < 4; ++ni) {
                int col = warp_n * 32 + ni * 8 + qid * 2;
                float bx = bias[col], by = bias[col + 1];
                if (r0 < NN) {
                    float2 v = make_float2(fmaxf(acc[mi][ni][0] + bx, 0.f),
                                           fmaxf(acc[mi][ni][1] + by, 0.f));
                    red_add_v2(g_pool + gA * HH + col, v);
                }
                if (r0 + 8 < NN) {
                    float2 v = make_float2(fmaxf(acc[mi][ni][2] + bx, 0.f),
                                           fmaxf(acc[mi][ni][3] + by, 0.f));
                    red_add_v2(g_pool + gB * HH + col, v);
                }
            }
        }
    }
}

// ======================= classifier =======================
__global__ void cls_kernel(const float* __restrict__ cw,
                           const float* __restrict__ cb,
                           float* __restrict__ out) {
    __shared__ float sh[HH];
    int g = blockIdx.x, j = threadIdx.x;
    float inv = 1.0f / fmaxf(g_gcnt[g], 1.0f);
    sh[j] = g_pool[g * HH + j] * inv;
    __syncthreads();
    float acc = 0.f;
    #pragma unroll 8
    for (int k = 0; k < HH; ++k)
        acc += sh[k] * cw[(size_t)j * HH + k];
    out[g * HH + j] = acc + cb[j];
}

// ======================= launch =======================
extern "C" void kernel_launch(void* const* d_in, const int* in_sizes, int n_in,
                              void* d_out, int out_size) {
    const float* x    = (const float*)d_in[0];
    const int*   ei   = (const int*)d_in[1];    // int32 (JAX x64 disabled)
    const int*   batch= (const int*)d_in[2];    // int32
    const float* wl1 = (const float*)d_in[3];
    const float* b1  = (const float*)d_in[4];
    const float* wr1 = (const float*)d_in[5];
    const float* wl2 = (const float*)d_in[6];
    const float* b2  = (const float*)d_in[7];
    const float* wr2 = (const float*)d_in[8];
    const float* cw  = (const float*)d_in[9];
    const float* cb  = (const float*)d_in[10];
    float* out = (float*)d_out;

    cudaFuncSetAttribute(gemm_mma, cudaFuncAttributeMaxDynamicSharedMemorySize, SM_TOTAL);

    const int egrid  = (NE + 255) / 256;          // 3125
    const int gmgrid = (NN + 127) / 128;          // 391
    const int wgrid  = (NN + 7) / 8;              // 6250
    const int cvgrid = (NN * HH / 8 + 255) / 256; // 3125

    // prep (zeros + fp16 conversions) then CSR build
    prep_kernel<<<cvgrid, 256>>>(x, ei, wl1, wr1, wl2, wr2);
    hist_kernel<<<egrid, 256>>>(ei);
    scan1_kernel<<<NBLK, 256>>>();
    scan23_kernel<<<NBLK, 256>>>(batch);
    fill_kernel<<<egrid, 256>>>(ei);

    // layer 1
    agg_kernel<<<wgrid, 256>>>(0);
    gemm_mma<<<gmgrid, 256, SM_TOTAL>>>(b1, batch, 0);

    // layer 2 (pool fused into gemm epilogue)
    agg_kernel<<<wgrid, 256>>>(1);
    gemm_mma<<<gmgrid, 256, SM_TOTAL>>>(b2, batch, 1);

    // classifier
    cls_kernel<<<NG, HH>>>(cw, cb, out);
}